// round 10
// baseline (speedup 1.0000x reference)
#include <cuda_runtime.h>
#include <cuda_bf16.h>
#include <cstdint>

// Problem constants
#define ZB     2
#define NTOK   2048
#define DMODEL 1024
#define HEADS  16
#define DK     64
#define ROWS   (ZB * NTOK)          // 4096
#define SCALE  0.125f               // DK^-0.5
#define ZH     (ZB * HEADS)         // 32

// ---------------------------------------------------------------------------
// Device scratch (no runtime allocation allowed)
// ---------------------------------------------------------------------------
__device__ __nv_bfloat16 g_Xh[ROWS * DMODEL];   // x split
__device__ __nv_bfloat16 g_Xl[ROWS * DMODEL];
__device__ __nv_bfloat16 g_BQh[HEADS * DK * DMODEL];  // proj split, [h][n][k]
__device__ __nv_bfloat16 g_BQl[HEADS * DK * DMODEL];
__device__ __nv_bfloat16 g_BKh[HEADS * DK * DMODEL];
__device__ __nv_bfloat16 g_BKl[HEADS * DK * DMODEL];
__device__ __nv_bfloat16 g_BVh[HEADS * DK * DMODEL];
__device__ __nv_bfloat16 g_BVl[HEADS * DK * DMODEL];
__device__ __nv_bfloat16 g_Wh[DMODEL * DMODEL]; // out_w split ([n][k] = native)
__device__ __nv_bfloat16 g_Wl[DMODEL * DMODEL];
__device__ __nv_bfloat16 g_Ch[ROWS * DMODEL];   // ctx split (attention output)
__device__ __nv_bfloat16 g_Cl[ROWS * DMODEL];

// pre-split QKV (written directly by GEMM epilogues)
__device__ __nv_bfloat16 g_Qh[ZH * NTOK * DK];  // [zh][n][dk], SCALE folded
__device__ __nv_bfloat16 g_Ql[ZH * NTOK * DK];
__device__ __nv_bfloat16 g_Kh[ZH * NTOK * DK];  // [zh][key][dk]
__device__ __nv_bfloat16 g_Kl[ZH * NTOK * DK];
__device__ __nv_bfloat16 g_Vth[ZH * DK * NTOK]; // transposed: [zh][dk][key]
__device__ __nv_bfloat16 g_Vtl[ZH * DK * NTOK];

extern __shared__ unsigned char smem_dyn[];

// ---------------------------------------------------------------------------
// helpers
// ---------------------------------------------------------------------------
__device__ __forceinline__ uint32_t packb(__nv_bfloat16 x, __nv_bfloat16 y) {
    return (uint32_t)__bfloat16_as_ushort(x) |
           ((uint32_t)__bfloat16_as_ushort(y) << 16);
}
__device__ __forceinline__ void split1(float x, __nv_bfloat16& h, __nv_bfloat16& l) {
    h = __float2bfloat16(x);
    l = __float2bfloat16(x - __bfloat162float(h));
}
__device__ __forceinline__ void split2(float x, float y, uint32_t& hi, uint32_t& lo) {
    __nv_bfloat16 xh, xl, yh, yl;
    split1(x, xh, xl);
    split1(y, yh, yl);
    hi = packb(xh, yh);
    lo = packb(xl, yl);
}

__device__ __forceinline__ void mma4(float* C, const uint32_t* a,
                                     uint32_t b0, uint32_t b1)
{
    asm volatile(
        "mma.sync.aligned.m16n8k16.row.col.f32.bf16.bf16.f32 "
        "{%0,%1,%2,%3},{%4,%5,%6,%7},{%8,%9},{%0,%1,%2,%3};\n"
        : "+f"(C[0]), "+f"(C[1]), "+f"(C[2]), "+f"(C[3])
        : "r"(a[0]), "r"(a[1]), "r"(a[2]), "r"(a[3]), "r"(b0), "r"(b1));
}

__device__ __forceinline__ void ldsm4(uint32_t* r, uint32_t addr) {
    asm volatile("ldmatrix.sync.aligned.m8n8.x4.shared.b16 {%0,%1,%2,%3}, [%4];"
                 : "=r"(r[0]), "=r"(r[1]), "=r"(r[2]), "=r"(r[3]) : "r"(addr));
}

__device__ __forceinline__ void cp_async16(uint32_t dst, const void* src) {
    asm volatile("cp.async.cg.shared.global [%0], [%1], 16;" :: "r"(dst), "l"(src));
}
__device__ __forceinline__ void cp_async4(uint32_t dst, const void* src) {
    asm volatile("cp.async.ca.shared.global [%0], [%1], 4;" :: "r"(dst), "l"(src));
}
__device__ __forceinline__ void cp_commit() {
    asm volatile("cp.async.commit_group;");
}
template <int N>
__device__ __forceinline__ void cp_wait() {
    asm volatile("cp.async.wait_group %0;" :: "n"(N));
}

// ---------------------------------------------------------------------------
// Vectorized elementwise split: fp32 -> (hi, lo) bf16, 4 elems/thread/iter
// ---------------------------------------------------------------------------
__global__ void split_any4_kernel(const float4* __restrict__ in,
                                  uint2* __restrict__ hi,
                                  uint2* __restrict__ lo, int n4)
{
    for (int i = blockIdx.x * blockDim.x + threadIdx.x; i < n4;
         i += gridDim.x * blockDim.x) {
        float4 v = in[i];
        uint32_t h0, l0, h1, l1;
        split2(v.x, v.y, h0, l0);
        split2(v.z, v.w, h1, l1);
        hi[i] = make_uint2(h0, h1);
        lo[i] = make_uint2(l0, l1);
    }
}

// ---------------------------------------------------------------------------
// Proj split + transpose for Q,K,V in one launch (blockIdx.z selects).
// proj[h][d][n] (fp32) -> B[h][n][d] hi/lo (bf16). grid=(16, HEADS, 3)
// ---------------------------------------------------------------------------
__global__ __launch_bounds__(256) void split_proj3_kernel(
    const float* __restrict__ pq, const float* __restrict__ pk,
    const float* __restrict__ pv,
    __nv_bfloat16* __restrict__ qh, __nv_bfloat16* __restrict__ ql,
    __nv_bfloat16* __restrict__ kh, __nv_bfloat16* __restrict__ kl,
    __nv_bfloat16* __restrict__ vh, __nv_bfloat16* __restrict__ vl)
{
    const int dt = blockIdx.x;
    const int h  = blockIdx.y;
    const int w  = blockIdx.z;
    const float* proj = (w == 0) ? pq : (w == 1) ? pk : pv;
    __nv_bfloat16* Bh = (w == 0) ? qh : (w == 1) ? kh : vh;
    __nv_bfloat16* Bl = (w == 0) ? ql : (w == 1) ? kl : vl;

    const int tid = threadIdx.x;
    __shared__ float tile[64][65];

    const float* src = proj + ((size_t)h * DMODEL + dt * 64) * DK;
    #pragma unroll
    for (int it = 0; it < 4; it++) {
        int i4 = tid + it * 256;
        int r  = i4 >> 4;
        int c4 = (i4 & 15) * 4;
        float4 v = *(const float4*)(src + (size_t)r * DK + c4);
        tile[r][c4 + 0] = v.x; tile[r][c4 + 1] = v.y;
        tile[r][c4 + 2] = v.z; tile[r][c4 + 3] = v.w;
    }
    __syncthreads();
    #pragma unroll
    for (int it = 0; it < 16; it++) {
        int o = tid + it * 256;
        int n = o >> 6;
        int j = o & 63;
        float x = tile[j][n];
        __nv_bfloat16 hh, ll;
        split1(x, hh, ll);
        size_t idx = ((size_t)h * DK + n) * DMODEL + dt * 64 + j;
        Bh[idx] = hh;
        Bl[idx] = ll;
    }
}

// ---------------------------------------------------------------------------
// bf16x3 MMA GEMM core: 128x64 block tile, K chunks of 32, cp.async 2-stage,
// ldmatrix fragment loads, MMA pass-reordering for accumulator ILP.
// 256 threads = 8 warps, warp = 16 rows x 64 cols.
// Stage layout (stride 40 elems = 80 B rows, conflict-free for LDSM):
//   sAh 128x40 (10240 B) | sAl 10240 | sBh 64x40 (5120) | sBl 5120  = 30720 B
// ---------------------------------------------------------------------------
#define G_AH      0
#define G_AL      10240
#define G_BH      20480
#define G_BL      25600
#define G_STAGE   30720

__device__ __forceinline__ void gemm_bf3_core(
    const __nv_bfloat16* __restrict__ Ahb, const __nv_bfloat16* __restrict__ Alb,
    const __nv_bfloat16* __restrict__ Bhb, const __nv_bfloat16* __restrict__ Blb,
    float O[8][4])
{
    const int tid  = threadIdx.x;
    const int warp = tid >> 5;
    const int lane = tid & 31;
    const uint32_t sbase = (uint32_t)__cvta_generic_to_shared(smem_dyn);

    // LDSM per-lane offsets
    const int rA = lane & 15, cA = (lane & 16) >> 1;          // A tiles
    const int rB = (lane & 7) | ((lane & 16) >> 1), cB = lane & 8;  // B tiles
    const uint32_t offA = (uint32_t)(((warp * 16 + rA) * 40 + cA) * 2);
    const uint32_t offB = (uint32_t)((rB * 40 + cB) * 2);

    // cp.async coordinates
    const int ar0 = tid >> 2, ac = (tid & 3);                 // A: 2 chunks/thread
    const int ar1 = (tid + 256) >> 2;
    const int br  = tid >> 2;                                  // B: 1 chunk/thread

    auto issue = [&](int kcid, int stage) {
        const uint32_t sb = sbase + stage * G_STAGE;
        const int kc = kcid * 32;
        cp_async16(sb + G_AH + ar0 * 80 + ac * 16, Ahb + (size_t)ar0 * DMODEL + kc + ac * 8);
        cp_async16(sb + G_AL + ar0 * 80 + ac * 16, Alb + (size_t)ar0 * DMODEL + kc + ac * 8);
        cp_async16(sb + G_AH + ar1 * 80 + ac * 16, Ahb + (size_t)ar1 * DMODEL + kc + ac * 8);
        cp_async16(sb + G_AL + ar1 * 80 + ac * 16, Alb + (size_t)ar1 * DMODEL + kc + ac * 8);
        cp_async16(sb + G_BH + br * 80 + ac * 16,  Bhb + (size_t)br * DMODEL + kc + ac * 8);
        cp_async16(sb + G_BL + br * 80 + ac * 16,  Blb + (size_t)br * DMODEL + kc + ac * 8);
    };

    issue(0, 0);
    cp_commit();

    for (int i = 0; i < 32; i++) {
        if (i + 1 < 32) {
            issue(i + 1, (i + 1) & 1);
            cp_commit();
            cp_wait<1>();
        } else {
            cp_wait<0>();
        }
        __syncthreads();

        const uint32_t sb = sbase + (i & 1) * G_STAGE;
        #pragma unroll
        for (int ks = 0; ks < 2; ks++) {
            uint32_t ah[4], al[4];
            ldsm4(ah, sb + G_AH + offA + ks * 32);
            ldsm4(al, sb + G_AL + offA + ks * 32);
            uint32_t bh[4][4], bl[4][4];
            #pragma unroll
            for (int p = 0; p < 4; p++) {
                uint32_t kb = sb + offB + p * 1280 + ks * 32;
                ldsm4(bh[p], kb + G_BH);
                ldsm4(bl[p], kb + G_BL);
            }
            // pass 1: hi*hi — 8 independent accumulator chains
            #pragma unroll
            for (int p = 0; p < 4; p++) {
                mma4(O[2 * p],     ah, bh[p][0], bh[p][1]);
                mma4(O[2 * p + 1], ah, bh[p][2], bh[p][3]);
            }
            // pass 2: hi*lo
            #pragma unroll
            for (int p = 0; p < 4; p++) {
                mma4(O[2 * p],     ah, bl[p][0], bl[p][1]);
                mma4(O[2 * p + 1], ah, bl[p][2], bl[p][3]);
            }
            // pass 3: lo*hi
            #pragma unroll
            for (int p = 0; p < 4; p++) {
                mma4(O[2 * p],     al, bh[p][0], bh[p][1]);
                mma4(O[2 * p + 1], al, bh[p][2], bh[p][3]);
            }
        }
        __syncthreads();
    }
}

// Q projection: writes pre-split, pre-scaled Qh/Ql [zh][n][dk]
__global__ __launch_bounds__(256) void gemm_bf3_q(
    const __nv_bfloat16* __restrict__ Ah, const __nv_bfloat16* __restrict__ Al,
    const __nv_bfloat16* __restrict__ Bh, const __nv_bfloat16* __restrict__ Bl,
    const float* __restrict__ bias,
    __nv_bfloat16* __restrict__ Qh, __nv_bfloat16* __restrict__ Ql)
{
    const int h  = blockIdx.x;
    const int mb = blockIdx.y;
    float O[8][4] = {};
    gemm_bf3_core(Ah + (size_t)mb * 128 * DMODEL, Al + (size_t)mb * 128 * DMODEL,
                  Bh + (size_t)h * DK * DMODEL,   Bl + (size_t)h * DK * DMODEL, O);

    const int warp = threadIdx.x >> 5, lane = threadIdx.x & 31;
    const int g = lane >> 2, tg = lane & 3;
    const int row0 = mb * 128 + warp * 16 + g, row1 = row0 + 8;
    const int z = row0 >> 11, n0 = row0 & (NTOK - 1), n1 = row1 & (NTOK - 1);
    const int zh = z * HEADS + h;

    #pragma unroll
    for (int nt = 0; nt < 8; nt++) {
        int col = nt * 8 + 2 * tg;
        float b0 = bias[h * DK + col], b1 = bias[h * DK + col + 1];
        uint32_t hh, ll;
        size_t i0 = ((size_t)zh * NTOK + n0) * DK + col;
        size_t i1 = ((size_t)zh * NTOK + n1) * DK + col;
        split2((O[nt][0] + b0) * SCALE, (O[nt][1] + b1) * SCALE, hh, ll);
        *(uint32_t*)&Qh[i0] = hh; *(uint32_t*)&Ql[i0] = ll;
        split2((O[nt][2] + b0) * SCALE, (O[nt][3] + b1) * SCALE, hh, ll);
        *(uint32_t*)&Qh[i1] = hh; *(uint32_t*)&Ql[i1] = ll;
    }
}

// K projection: writes pre-split Kh/Kl [zh][key][dk]
__global__ __launch_bounds__(256) void gemm_bf3_k(
    const __nv_bfloat16* __restrict__ Ah, const __nv_bfloat16* __restrict__ Al,
    const __nv_bfloat16* __restrict__ Bh, const __nv_bfloat16* __restrict__ Bl,
    const float* __restrict__ bias,
    __nv_bfloat16* __restrict__ Kh, __nv_bfloat16* __restrict__ Kl)
{
    const int h  = blockIdx.x;
    const int mb = blockIdx.y;
    float O[8][4] = {};
    gemm_bf3_core(Ah + (size_t)mb * 128 * DMODEL, Al + (size_t)mb * 128 * DMODEL,
                  Bh + (size_t)h * DK * DMODEL,   Bl + (size_t)h * DK * DMODEL, O);

    const int warp = threadIdx.x >> 5, lane = threadIdx.x & 31;
    const int g = lane >> 2, tg = lane & 3;
    const int row0 = mb * 128 + warp * 16 + g, row1 = row0 + 8;
    const int z = row0 >> 11, n0 = row0 & (NTOK - 1), n1 = row1 & (NTOK - 1);
    const int zh = z * HEADS + h;

    #pragma unroll
    for (int nt = 0; nt < 8; nt++) {
        int col = nt * 8 + 2 * tg;
        float b0 = bias[h * DK + col], b1 = bias[h * DK + col + 1];
        uint32_t hh, ll;
        size_t i0 = ((size_t)zh * NTOK + n0) * DK + col;
        size_t i1 = ((size_t)zh * NTOK + n1) * DK + col;
        split2(O[nt][0] + b0, O[nt][1] + b1, hh, ll);
        *(uint32_t*)&Kh[i0] = hh; *(uint32_t*)&Kl[i0] = ll;
        split2(O[nt][2] + b0, O[nt][3] + b1, hh, ll);
        *(uint32_t*)&Kh[i1] = hh; *(uint32_t*)&Kl[i1] = ll;
    }
}

// V projection: writes pre-split TRANSPOSED Vth/Vtl [zh][dk][key]
__global__ __launch_bounds__(256) void gemm_bf3_v(
    const __nv_bfloat16* __restrict__ Ah, const __nv_bfloat16* __restrict__ Al,
    const __nv_bfloat16* __restrict__ Bh, const __nv_bfloat16* __restrict__ Bl,
    const float* __restrict__ bias,
    __nv_bfloat16* __restrict__ Vth, __nv_bfloat16* __restrict__ Vtl)
{
    const int h  = blockIdx.x;
    const int mb = blockIdx.y;
    float O[8][4] = {};
    gemm_bf3_core(Ah + (size_t)mb * 128 * DMODEL, Al + (size_t)mb * 128 * DMODEL,
                  Bh + (size_t)h * DK * DMODEL,   Bl + (size_t)h * DK * DMODEL, O);

    const int warp = threadIdx.x >> 5, lane = threadIdx.x & 31;
    const int g = lane >> 2, tg = lane & 3;
    const int row0 = mb * 128 + warp * 16 + g, row1 = row0 + 8;
    const int z = row0 >> 11, n0 = row0 & (NTOK - 1), n1 = row1 & (NTOK - 1);
    const size_t baseT = (size_t)(z * HEADS + h) * DK * NTOK;

    #pragma unroll
    for (int nt = 0; nt < 8; nt++) {
        int col = nt * 8 + 2 * tg;
        float b0 = bias[h * DK + col], b1 = bias[h * DK + col + 1];
        #pragma unroll
        for (int j = 0; j < 2; j++) {
            float v0 = O[nt][j]     + (j ? b1 : b0);
            float v1 = O[nt][2 + j] + (j ? b1 : b0);
            __nv_bfloat16 hh, ll;
            split1(v0, hh, ll);
            Vth[baseT + (size_t)(col + j) * NTOK + n0] = hh;
            Vtl[baseT + (size_t)(col + j) * NTOK + n0] = ll;
            split1(v1, hh, ll);
            Vth[baseT + (size_t)(col + j) * NTOK + n1] = hh;
            Vtl[baseT + (size_t)(col + j) * NTOK + n1] = ll;
        }
    }
}

// ---------------------------------------------------------------------------
// Flash attention: bf16x3 MMA + cp.async 2-stage pipeline + ldmatrix frags,
// MMA pass-reordering for accumulator ILP.
// Block = 128 threads (4 warps), 64 queries/block. grid = (NTOK/64, ZH)
// ---------------------------------------------------------------------------
#define TILE_B      9216        // 64 * 72 * 2
#define STAGE_B     37120       // 4*TILE_B + 256
#define OFF_KH      0
#define OFF_KL      (TILE_B)
#define OFF_VH      (2 * TILE_B)
#define OFF_VL      (3 * TILE_B)
#define OFF_MK      (4 * TILE_B)

__global__ __launch_bounds__(128) void attn_mma(
    const __nv_bfloat16* __restrict__ Qh_g, const __nv_bfloat16* __restrict__ Ql_g,
    const __nv_bfloat16* __restrict__ Kh_g, const __nv_bfloat16* __restrict__ Kl_g,
    const __nv_bfloat16* __restrict__ Vth_g, const __nv_bfloat16* __restrict__ Vtl_g,
    const int* __restrict__ mask,
    __nv_bfloat16* __restrict__ Ch, __nv_bfloat16* __restrict__ Cl)
{
    const int qt   = blockIdx.x;
    const int zh   = blockIdx.y;
    const int z    = zh >> 4;
    const int h    = zh & 15;
    const int tid  = threadIdx.x;
    const int warp = tid >> 5;
    const int lane = tid & 31;
    const int g    = lane >> 2;
    const int tg   = lane & 3;

    typedef __nv_bfloat16(*tile_t)[72];
    const size_t base  = (size_t)zh * NTOK * DK;
    const size_t baseT = (size_t)zh * DK * NTOK;
    const uint32_t smem_u32 = (uint32_t)__cvta_generic_to_shared(smem_dyn);

    // LDSM per-lane offsets (stride 72 elems = 144 B)
    const int rA = lane & 15, cA = (lane & 16) >> 1;
    const int rB = (lane & 7) | ((lane & 16) >> 1), cB = lane & 8;
    const uint32_t offQ = (uint32_t)(((warp * 16 + rA) * 72 + cA) * 2);
    const uint32_t offF = (uint32_t)((rB * 72 + cB) * 2);

    // per-thread tile-load coordinates (4 uint4 rows per array)
    const int lrow[4] = { tid >> 3, (tid + 128) >> 3, (tid + 256) >> 3, (tid + 384) >> 3 };
    const int lc8 = (tid & 7) * 8;

    // ---- stage Q hi/lo tiles into stage-0 smem, extract frags via LDSM ----
    {
        tile_t sQh = (tile_t)(smem_dyn + OFF_KH);
        tile_t sQl = (tile_t)(smem_dyn + OFF_KL);
        const __nv_bfloat16* gq_h = Qh_g + base + (size_t)qt * 64 * DK;
        const __nv_bfloat16* gq_l = Ql_g + base + (size_t)qt * 64 * DK;
        #pragma unroll
        for (int it = 0; it < 4; it++) {
            int row = lrow[it];
            *(uint4*)&sQh[row][lc8] = *(const uint4*)(gq_h + (size_t)row * DK + lc8);
            *(uint4*)&sQl[row][lc8] = *(const uint4*)(gq_l + (size_t)row * DK + lc8);
        }
    }
    __syncthreads();

    uint32_t Qh[4][4], Ql[4][4];
    #pragma unroll
    for (int kk = 0; kk < 4; kk++) {
        ldsm4(Qh[kk], smem_u32 + OFF_KH + offQ + kk * 32);
        ldsm4(Ql[kk], smem_u32 + OFF_KL + offQ + kk * 32);
    }
    __syncthreads();

    // ---- tile issuer (cp.async) ----
    auto issue_tile = [&](int kt, int stage) {
        const uint32_t sb = smem_u32 + stage * STAGE_B;
        const __nv_bfloat16* gkh = Kh_g + base + (size_t)kt * 64 * DK;
        const __nv_bfloat16* gkl = Kl_g + base + (size_t)kt * 64 * DK;
        const __nv_bfloat16* gvh = Vth_g + baseT + kt * 64;
        const __nv_bfloat16* gvl = Vtl_g + baseT + kt * 64;
        #pragma unroll
        for (int it = 0; it < 4; it++) {
            int row = lrow[it];
            uint32_t rowoff = row * 144 + lc8 * 2;
            cp_async16(sb + OFF_KH + rowoff, gkh + (size_t)row * DK + lc8);
            cp_async16(sb + OFF_KL + rowoff, gkl + (size_t)row * DK + lc8);
            cp_async16(sb + OFF_VH + rowoff, gvh + (size_t)row * NTOK + lc8);
            cp_async16(sb + OFF_VL + rowoff, gvl + (size_t)row * NTOK + lc8);
        }
        if (tid < 64)
            cp_async4(sb + OFF_MK + tid * 4, mask + z * NTOK + kt * 64 + tid);
    };

    float O[8][4];
    #pragma unroll
    for (int nt = 0; nt < 8; nt++)
        O[nt][0] = O[nt][1] = O[nt][2] = O[nt][3] = 0.f;
    float m0 = -1e30f, m1 = -1e30f, l0 = 0.f, l1 = 0.f;

    issue_tile(0, 0);
    cp_commit();

    for (int kt = 0; kt < NTOK / 64; kt++) {
        const int cur = kt & 1;
        if (kt + 1 < NTOK / 64) {
            issue_tile(kt + 1, cur ^ 1);
            cp_commit();
            cp_wait<1>();
        } else {
            cp_wait<0>();
        }
        __syncthreads();

        const uint32_t sb = smem_u32 + cur * STAGE_B;
        int* smk = (int*)(smem_dyn + cur * STAGE_B + OFF_MK);

        // ---- S = Q x K^T (bf16x3, pass-reordered) ----
        float S[8][4];
        #pragma unroll
        for (int nt = 0; nt < 8; nt++)
            S[nt][0] = S[nt][1] = S[nt][2] = S[nt][3] = 0.f;
        #pragma unroll
        for (int kk = 0; kk < 4; kk++) {
            uint32_t bh[4][4], bl[4][4];
            #pragma unroll
            for (int p = 0; p < 4; p++) {
                uint32_t kbb = sb + offF + p * 2304 + kk * 32;
                ldsm4(bh[p], kbb + OFF_KH);
                ldsm4(bl[p], kbb + OFF_KL);
            }
            #pragma unroll
            for (int p = 0; p < 4; p++) {
                mma4(S[2*p],   Qh[kk], bh[p][0], bh[p][1]);
                mma4(S[2*p+1], Qh[kk], bh[p][2], bh[p][3]);
            }
            #pragma unroll
            for (int p = 0; p < 4; p++) {
                mma4(S[2*p],   Qh[kk], bl[p][0], bl[p][1]);
                mma4(S[2*p+1], Qh[kk], bl[p][2], bl[p][3]);
            }
            #pragma unroll
            for (int p = 0; p < 4; p++) {
                mma4(S[2*p],   Ql[kk], bh[p][0], bh[p][1]);
                mma4(S[2*p+1], Ql[kk], bh[p][2], bh[p][3]);
            }
        }

        // ---- mask + online softmax ----
        float mx0 = -1e30f, mx1 = -1e30f;
        #pragma unroll
        for (int nt = 0; nt < 8; nt++) {
            #pragma unroll
            for (int j = 0; j < 2; j++) {
                int key = nt * 8 + 2 * tg + j;
                bool ok = smk[key] != 0;
                float v0 = ok ? S[nt][j]     : -1e9f;
                float v1 = ok ? S[nt][2 + j] : -1e9f;
                S[nt][j] = v0; S[nt][2 + j] = v1;
                mx0 = fmaxf(mx0, v0); mx1 = fmaxf(mx1, v1);
            }
        }
        mx0 = fmaxf(mx0, __shfl_xor_sync(0xffffffffu, mx0, 1));
        mx0 = fmaxf(mx0, __shfl_xor_sync(0xffffffffu, mx0, 2));
        mx1 = fmaxf(mx1, __shfl_xor_sync(0xffffffffu, mx1, 1));
        mx1 = fmaxf(mx1, __shfl_xor_sync(0xffffffffu, mx1, 2));

        float mn0 = fmaxf(m0, mx0), mn1 = fmaxf(m1, mx1);
        float corr0 = __expf(m0 - mn0), corr1 = __expf(m1 - mn1);
        m0 = mn0; m1 = mn1;

        float ls0 = 0.f, ls1 = 0.f;
        #pragma unroll
        for (int nt = 0; nt < 8; nt++) {
            S[nt][0] = __expf(S[nt][0] - m0); ls0 += S[nt][0];
            S[nt][1] = __expf(S[nt][1] - m0); ls0 += S[nt][1];
            S[nt][2] = __expf(S[nt][2] - m1); ls1 += S[nt][2];
            S[nt][3] = __expf(S[nt][3] - m1); ls1 += S[nt][3];
        }
        ls0 += __shfl_xor_sync(0xffffffffu, ls0, 1);
        ls0 += __shfl_xor_sync(0xffffffffu, ls0, 2);
        ls1 += __shfl_xor_sync(0xffffffffu, ls1, 1);
        ls1 += __shfl_xor_sync(0xffffffffu, ls1, 2);
        l0 = l0 * corr0 + ls0;
        l1 = l1 * corr1 + ls1;

        #pragma unroll
        for (int nt = 0; nt < 8; nt++) {
            O[nt][0] *= corr0; O[nt][1] *= corr0;
            O[nt][2] *= corr1; O[nt][3] *= corr1;
        }

        // ---- O += P x V (bf16x3, pass-reordered) ----
        #pragma unroll
        for (int kk = 0; kk < 4; kk++) {
            uint32_t ah[4], al[4];
            split2(S[2 * kk][0],     S[2 * kk][1],     ah[0], al[0]);
            split2(S[2 * kk][2],     S[2 * kk][3],     ah[1], al[1]);
            split2(S[2 * kk + 1][0], S[2 * kk + 1][1], ah[2], al[2]);
            split2(S[2 * kk + 1][2], S[2 * kk + 1][3], ah[3], al[3]);
            uint32_t bh[4][4], bl[4][4];
            #pragma unroll
            for (int p = 0; p < 4; p++) {
                uint32_t vbb = sb + offF + p * 2304 + kk * 32;
                ldsm4(bh[p], vbb + OFF_VH);
                ldsm4(bl[p], vbb + OFF_VL);
            }
            #pragma unroll
            for (int p = 0; p < 4; p++) {
                mma4(O[2*p],   ah, bh[p][0], bh[p][1]);
                mma4(O[2*p+1], ah, bh[p][2], bh[p][3]);
            }
            #pragma unroll
            for (int p = 0; p < 4; p++) {
                mma4(O[2*p],   ah, bl[p][0], bl[p][1]);
                mma4(O[2*p+1], ah, bl[p][2], bl[p][3]);
            }
            #pragma unroll
            for (int p = 0; p < 4; p++) {
                mma4(O[2*p],   al, bh[p][0], bh[p][1]);
                mma4(O[2*p+1], al, bh[p][2], bh[p][3]);
            }
        }
        __syncthreads();
    }

    // ---- epilogue: normalize, zero invalid queries, write SPLIT ctx ----
    const int tok0 = qt * 64 + warp * 16 + g;
    const int tok1 = tok0 + 8;
    const int qv0 = mask[z * NTOK + tok0];
    const int qv1 = mask[z * NTOK + tok1];
    const float inv0 = (qv0 && l0 > 0.f) ? 1.0f / l0 : 0.f;
    const float inv1 = (qv1 && l1 > 0.f) ? 1.0f / l1 : 0.f;

    #pragma unroll
    for (int nt = 0; nt < 8; nt++) {
        int dk = nt * 8 + 2 * tg;
        size_t i0 = ((size_t)(z * NTOK + tok0)) * DMODEL + h * DK + dk;
        size_t i1 = ((size_t)(z * NTOK + tok1)) * DMODEL + h * DK + dk;
        uint32_t hh, ll;
        split2(O[nt][0] * inv0, O[nt][1] * inv0, hh, ll);
        *(uint32_t*)&Ch[i0] = hh; *(uint32_t*)&Cl[i0] = ll;
        split2(O[nt][2] * inv1, O[nt][3] * inv1, hh, ll);
        *(uint32_t*)&Ch[i1] = hh; *(uint32_t*)&Cl[i1] = ll;
    }
}

// ---------------------------------------------------------------------------
// Out-proj GEMM (reads split ctx, writes fp32 out)
// ---------------------------------------------------------------------------
__global__ __launch_bounds__(256) void gemm_bf3_out(
    const __nv_bfloat16* __restrict__ Ah, const __nv_bfloat16* __restrict__ Al,
    const __nv_bfloat16* __restrict__ Bh, const __nv_bfloat16* __restrict__ Bl,
    float* __restrict__ Out)
{
    const int cb = blockIdx.x;
    const int mb = blockIdx.y;
    float O[8][4] = {};
    gemm_bf3_core(Ah + (size_t)mb * 128 * DMODEL, Al + (size_t)mb * 128 * DMODEL,
                  Bh + (size_t)cb * 64 * DMODEL,  Bl + (size_t)cb * 64 * DMODEL, O);

    const int warp = threadIdx.x >> 5, lane = threadIdx.x & 31;
    const int g = lane >> 2, tg = lane & 3;
    const int row0 = mb * 128 + warp * 16 + g, row1 = row0 + 8;

    #pragma unroll
    for (int nt = 0; nt < 8; nt++) {
        int col = cb * 64 + nt * 8 + 2 * tg;
        *(float2*)&Out[(size_t)row0 * DMODEL + col] = make_float2(O[nt][0], O[nt][1]);
        *(float2*)&Out[(size_t)row1 * DMODEL + col] = make_float2(O[nt][2], O[nt][3]);
    }
}

// ---------------------------------------------------------------------------
// Host entry
// ---------------------------------------------------------------------------
extern "C" void kernel_launch(void* const* d_in, const int* in_sizes, int n_in,
                              void* d_out, int out_size)
{
    const float* x     = (const float*)d_in[0];
    const int*   mask  = (const int*)  d_in[1];
    const float* qproj = (const float*)d_in[2];
    const float* kproj = (const float*)d_in[3];
    const float* vproj = (const float*)d_in[4];
    const float* qbias = (const float*)d_in[5];
    const float* kbias = (const float*)d_in[6];
    const float* vbias = (const float*)d_in[7];
    const float* outw  = (const float*)d_in[8];
    float* out = (float*)d_out;

    __nv_bfloat16 *Xh, *Xl, *BQh, *BQl, *BKh, *BKl, *BVh, *BVl, *Wh, *Wl;
    __nv_bfloat16 *Ch, *Cl, *Qh, *Ql, *Kh, *Kl, *Vth, *Vtl;
    cudaGetSymbolAddress((void**)&Xh,  g_Xh);
    cudaGetSymbolAddress((void**)&Xl,  g_Xl);
    cudaGetSymbolAddress((void**)&BQh, g_BQh);
    cudaGetSymbolAddress((void**)&BQl, g_BQl);
    cudaGetSymbolAddress((void**)&BKh, g_BKh);
    cudaGetSymbolAddress((void**)&BKl, g_BKl);
    cudaGetSymbolAddress((void**)&BVh, g_BVh);
    cudaGetSymbolAddress((void**)&BVl, g_BVl);
    cudaGetSymbolAddress((void**)&Wh,  g_Wh);
    cudaGetSymbolAddress((void**)&Wl,  g_Wl);
    cudaGetSymbolAddress((void**)&Ch,  g_Ch);
    cudaGetSymbolAddress((void**)&Cl,  g_Cl);
    cudaGetSymbolAddress((void**)&Qh,  g_Qh);
    cudaGetSymbolAddress((void**)&Ql,  g_Ql);
    cudaGetSymbolAddress((void**)&Kh,  g_Kh);
    cudaGetSymbolAddress((void**)&Kl,  g_Kl);
    cudaGetSymbolAddress((void**)&Vth, g_Vth);
    cudaGetSymbolAddress((void**)&Vtl, g_Vtl);

    static bool attr_set = false;
    if (!attr_set) {
        cudaFuncSetAttribute(attn_mma,
                             cudaFuncAttributeMaxDynamicSharedMemorySize, 2 * STAGE_B);
        cudaFuncSetAttribute(gemm_bf3_q,
                             cudaFuncAttributeMaxDynamicSharedMemorySize, 2 * G_STAGE);
        cudaFuncSetAttribute(gemm_bf3_k,
                             cudaFuncAttributeMaxDynamicSharedMemorySize, 2 * G_STAGE);
        cudaFuncSetAttribute(gemm_bf3_v,
                             cudaFuncAttributeMaxDynamicSharedMemorySize, 2 * G_STAGE);
        cudaFuncSetAttribute(gemm_bf3_out,
                             cudaFuncAttributeMaxDynamicSharedMemorySize, 2 * G_STAGE);
        attr_set = true;
    }

    // input splits
    split_any4_kernel<<<1024, 256>>>((const float4*)x, (uint2*)Xh, (uint2*)Xl,
                                     ROWS * DMODEL / 4);
    split_proj3_kernel<<<dim3(DMODEL / 64, HEADS, 3), 256>>>(
        qproj, kproj, vproj, BQh, BQl, BKh, BKl, BVh, BVl);
    split_any4_kernel<<<512, 256>>>((const float4*)outw, (uint2*)Wh, (uint2*)Wl,
                                    DMODEL * DMODEL / 4);

    // QKV projections (tensor-core, pipelined, split epilogues)
    dim3 gq(HEADS, ROWS / 128);
    gemm_bf3_q<<<gq, 256, 2 * G_STAGE>>>(Xh, Xl, BQh, BQl, qbias, Qh, Ql);
    gemm_bf3_k<<<gq, 256, 2 * G_STAGE>>>(Xh, Xl, BKh, BKl, kbias, Kh, Kl);
    gemm_bf3_v<<<gq, 256, 2 * G_STAGE>>>(Xh, Xl, BVh, BVl, vbias, Vth, Vtl);

    // attention (tensor-core, cp.async pipelined, LDSM frags)
    attn_mma<<<dim3(NTOK / 64, ZH), 128, 2 * STAGE_B>>>(
        Qh, Ql, Kh, Kl, Vth, Vtl, mask, Ch, Cl);

    // output projection (tensor-core, pipelined)
    gemm_bf3_out<<<dim3(DMODEL / 64, ROWS / 128), 256, 2 * G_STAGE>>>(
        Ch, Cl, Wh, Wl, out);
}

// round 14
// speedup vs baseline: 1.0547x; 1.0547x over previous
#include <cuda_runtime.h>
#include <cuda_bf16.h>
#include <cstdint>

// Problem constants
#define ZB     2
#define NTOK   2048
#define DMODEL 1024
#define HEADS  16
#define DK     64
#define ROWS   (ZB * NTOK)          // 4096
#define SCALE  0.125f               // DK^-0.5
#define ZH     (ZB * HEADS)         // 32

// ---------------------------------------------------------------------------
// Device scratch (no runtime allocation allowed)
// ---------------------------------------------------------------------------
__device__ __nv_bfloat16 g_Xh[ROWS * DMODEL];   // x split
__device__ __nv_bfloat16 g_Xl[ROWS * DMODEL];
__device__ __nv_bfloat16 g_BQh[HEADS * DK * DMODEL];  // proj split, [h][n][k]
__device__ __nv_bfloat16 g_BQl[HEADS * DK * DMODEL];
__device__ __nv_bfloat16 g_BKh[HEADS * DK * DMODEL];
__device__ __nv_bfloat16 g_BKl[HEADS * DK * DMODEL];
__device__ __nv_bfloat16 g_BVh[HEADS * DK * DMODEL];
__device__ __nv_bfloat16 g_BVl[HEADS * DK * DMODEL];
__device__ __nv_bfloat16 g_Wh[DMODEL * DMODEL]; // out_w split ([n][k] = native)
__device__ __nv_bfloat16 g_Wl[DMODEL * DMODEL];
__device__ __nv_bfloat16 g_Ch[ROWS * DMODEL];   // ctx split (attention output)
__device__ __nv_bfloat16 g_Cl[ROWS * DMODEL];

// pre-split QKV (written directly by GEMM epilogues)
__device__ __nv_bfloat16 g_Qh[ZH * NTOK * DK];  // [zh][n][dk], SCALE folded
__device__ __nv_bfloat16 g_Ql[ZH * NTOK * DK];
__device__ __nv_bfloat16 g_Kh[ZH * NTOK * DK];  // [zh][key][dk]
__device__ __nv_bfloat16 g_Kl[ZH * NTOK * DK];
__device__ __nv_bfloat16 g_Vth[ZH * DK * NTOK]; // transposed: [zh][dk][key]
__device__ __nv_bfloat16 g_Vtl[ZH * DK * NTOK];

extern __shared__ unsigned char smem_dyn[];

// ---------------------------------------------------------------------------
// helpers
// ---------------------------------------------------------------------------
__device__ __forceinline__ uint32_t packb(__nv_bfloat16 x, __nv_bfloat16 y) {
    return (uint32_t)__bfloat16_as_ushort(x) |
           ((uint32_t)__bfloat16_as_ushort(y) << 16);
}
__device__ __forceinline__ void split1(float x, __nv_bfloat16& h, __nv_bfloat16& l) {
    h = __float2bfloat16(x);
    l = __float2bfloat16(x - __bfloat162float(h));
}
__device__ __forceinline__ void split2(float x, float y, uint32_t& hi, uint32_t& lo) {
    __nv_bfloat16 xh, xl, yh, yl;
    split1(x, xh, xl);
    split1(y, yh, yl);
    hi = packb(xh, yh);
    lo = packb(xl, yl);
}

__device__ __forceinline__ void mma4(float* C, const uint32_t* a,
                                     uint32_t b0, uint32_t b1)
{
    asm volatile(
        "mma.sync.aligned.m16n8k16.row.col.f32.bf16.bf16.f32 "
        "{%0,%1,%2,%3},{%4,%5,%6,%7},{%8,%9},{%0,%1,%2,%3};\n"
        : "+f"(C[0]), "+f"(C[1]), "+f"(C[2]), "+f"(C[3])
        : "r"(a[0]), "r"(a[1]), "r"(a[2]), "r"(a[3]), "r"(b0), "r"(b1));
}

__device__ __forceinline__ void ldsm4(uint32_t* r, uint32_t addr) {
    asm volatile("ldmatrix.sync.aligned.m8n8.x4.shared.b16 {%0,%1,%2,%3}, [%4];"
                 : "=r"(r[0]), "=r"(r[1]), "=r"(r[2]), "=r"(r[3]) : "r"(addr));
}

__device__ __forceinline__ void cp_async16(uint32_t dst, const void* src) {
    asm volatile("cp.async.cg.shared.global [%0], [%1], 16;" :: "r"(dst), "l"(src));
}
__device__ __forceinline__ void cp_async4(uint32_t dst, const void* src) {
    asm volatile("cp.async.ca.shared.global [%0], [%1], 4;" :: "r"(dst), "l"(src));
}
__device__ __forceinline__ void cp_commit() {
    asm volatile("cp.async.commit_group;");
}
template <int N>
__device__ __forceinline__ void cp_wait() {
    asm volatile("cp.async.wait_group %0;" :: "n"(N));
}

// ---------------------------------------------------------------------------
// Vectorized elementwise split: fp32 -> (hi, lo) bf16
// ---------------------------------------------------------------------------
__global__ void split_any4_kernel(const float4* __restrict__ in,
                                  uint2* __restrict__ hi,
                                  uint2* __restrict__ lo, int n4)
{
    for (int i = blockIdx.x * blockDim.x + threadIdx.x; i < n4;
         i += gridDim.x * blockDim.x) {
        float4 v = in[i];
        uint32_t h0, l0, h1, l1;
        split2(v.x, v.y, h0, l0);
        split2(v.z, v.w, h1, l1);
        hi[i] = make_uint2(h0, h1);
        lo[i] = make_uint2(l0, l1);
    }
}

// ---------------------------------------------------------------------------
// Proj split + transpose for Q,K,V in one launch (blockIdx.z selects).
// proj[h][d][n] (fp32) -> B[h][n][d] hi/lo (bf16). grid=(16, HEADS, 3)
// ---------------------------------------------------------------------------
__global__ __launch_bounds__(256) void split_proj3_kernel(
    const float* __restrict__ pq, const float* __restrict__ pk,
    const float* __restrict__ pv,
    __nv_bfloat16* __restrict__ qh, __nv_bfloat16* __restrict__ ql,
    __nv_bfloat16* __restrict__ kh, __nv_bfloat16* __restrict__ kl,
    __nv_bfloat16* __restrict__ vh, __nv_bfloat16* __restrict__ vl)
{
    const int dt = blockIdx.x;
    const int h  = blockIdx.y;
    const int w  = blockIdx.z;
    const float* proj = (w == 0) ? pq : (w == 1) ? pk : pv;
    __nv_bfloat16* Bh = (w == 0) ? qh : (w == 1) ? kh : vh;
    __nv_bfloat16* Bl = (w == 0) ? ql : (w == 1) ? kl : vl;

    const int tid = threadIdx.x;
    __shared__ float tile[64][65];

    const float* src = proj + ((size_t)h * DMODEL + dt * 64) * DK;
    #pragma unroll
    for (int it = 0; it < 4; it++) {
        int i4 = tid + it * 256;
        int r  = i4 >> 4;
        int c4 = (i4 & 15) * 4;
        float4 v = *(const float4*)(src + (size_t)r * DK + c4);
        tile[r][c4 + 0] = v.x; tile[r][c4 + 1] = v.y;
        tile[r][c4 + 2] = v.z; tile[r][c4 + 3] = v.w;
    }
    __syncthreads();
    #pragma unroll
    for (int it = 0; it < 16; it++) {
        int o = tid + it * 256;
        int n = o >> 6;
        int j = o & 63;
        float x = tile[j][n];
        __nv_bfloat16 hh, ll;
        split1(x, hh, ll);
        size_t idx = ((size_t)h * DK + n) * DMODEL + dt * 64 + j;
        Bh[idx] = hh;
        Bl[idx] = ll;
    }
}

// ---------------------------------------------------------------------------
// FUSED QKV bf16x3 MMA GEMM: one 128-row tile computes Q, K, V heads at once.
// A (Xh/Xl) staged ONCE per K-chunk; B slots for all three projections.
// 256 threads = 8 warps, warp = 16 rows x 64 cols x 3 outputs.
// Stage layout (stride 40 elems = 80 B rows, conflict-free for LDSM):
//   Ah 10240 | Al 10240 | w=0..2: { Bh 5120 | Bl 5120 }   = 51200 B/stage
// 3 stages = 153600 B dynamic SMEM, 1 CTA/SM.
// ---------------------------------------------------------------------------
#define F_AH     0
#define F_AL     10240
#define F_BB     20480       // + w*10240 (hi), +5120 (lo)
#define F_SZ     51200
#define F_SMEM   (3 * F_SZ)  // 153600

__global__ __launch_bounds__(256) void gemm_bf3_qkv_fused(
    const __nv_bfloat16* __restrict__ Xh, const __nv_bfloat16* __restrict__ Xl,
    const __nv_bfloat16* __restrict__ BQh, const __nv_bfloat16* __restrict__ BQl,
    const __nv_bfloat16* __restrict__ BKh, const __nv_bfloat16* __restrict__ BKl,
    const __nv_bfloat16* __restrict__ BVh, const __nv_bfloat16* __restrict__ BVl,
    const float* __restrict__ qbias, const float* __restrict__ kbias,
    const float* __restrict__ vbias,
    __nv_bfloat16* __restrict__ Qh_o, __nv_bfloat16* __restrict__ Ql_o,
    __nv_bfloat16* __restrict__ Kh_o, __nv_bfloat16* __restrict__ Kl_o,
    __nv_bfloat16* __restrict__ Vth_o, __nv_bfloat16* __restrict__ Vtl_o)
{
    const int h  = blockIdx.x;
    const int mb = blockIdx.y;
    const int tid  = threadIdx.x;
    const int warp = tid >> 5;
    const int lane = tid & 31;
    const uint32_t sbase = (uint32_t)__cvta_generic_to_shared(smem_dyn);

    const __nv_bfloat16* Ahb = Xh + (size_t)mb * 128 * DMODEL;
    const __nv_bfloat16* Alb = Xl + (size_t)mb * 128 * DMODEL;
    const __nv_bfloat16* Bh_[3] = { BQh + (size_t)h * DK * DMODEL,
                                    BKh + (size_t)h * DK * DMODEL,
                                    BVh + (size_t)h * DK * DMODEL };
    const __nv_bfloat16* Bl_[3] = { BQl + (size_t)h * DK * DMODEL,
                                    BKl + (size_t)h * DK * DMODEL,
                                    BVl + (size_t)h * DK * DMODEL };

    // LDSM per-lane offsets
    const int rA = lane & 15, cA = (lane & 16) >> 1;
    const int rB = (lane & 7) | ((lane & 16) >> 1), cB = lane & 8;
    const uint32_t offA = (uint32_t)(((warp * 16 + rA) * 40 + cA) * 2);
    const uint32_t offB = (uint32_t)((rB * 40 + cB) * 2);

    // cp.async coordinates
    const int ar0 = tid >> 2, ac = (tid & 3);
    const int ar1 = (tid + 256) >> 2;
    const int br  = tid >> 2;

    auto issue = [&](int kcid, int stage) {
        const uint32_t sb = sbase + stage * F_SZ;
        const int kc = kcid * 32;
        cp_async16(sb + F_AH + ar0 * 80 + ac * 16, Ahb + (size_t)ar0 * DMODEL + kc + ac * 8);
        cp_async16(sb + F_AL + ar0 * 80 + ac * 16, Alb + (size_t)ar0 * DMODEL + kc + ac * 8);
        cp_async16(sb + F_AH + ar1 * 80 + ac * 16, Ahb + (size_t)ar1 * DMODEL + kc + ac * 8);
        cp_async16(sb + F_AL + ar1 * 80 + ac * 16, Alb + (size_t)ar1 * DMODEL + kc + ac * 8);
        #pragma unroll
        for (int w = 0; w < 3; w++) {
            const uint32_t bw = sb + F_BB + w * 10240;
            cp_async16(bw + br * 80 + ac * 16,        Bh_[w] + (size_t)br * DMODEL + kc + ac * 8);
            cp_async16(bw + 5120 + br * 80 + ac * 16, Bl_[w] + (size_t)br * DMODEL + kc + ac * 8);
        }
    };

    float O[3][8][4];
    #pragma unroll
    for (int w = 0; w < 3; w++)
        #pragma unroll
        for (int nt = 0; nt < 8; nt++)
            O[w][nt][0] = O[w][nt][1] = O[w][nt][2] = O[w][nt][3] = 0.f;

    issue(0, 0); cp_commit();
    issue(1, 1); cp_commit();

    for (int i = 0; i < 32; i++) {
        if (i + 2 < 32) {
            issue(i + 2, (i + 2) % 3);
            cp_commit();
            cp_wait<2>();
        } else if (i + 1 < 32) {
            cp_wait<1>();
        } else {
            cp_wait<0>();
        }
        __syncthreads();

        const uint32_t sb = sbase + (i % 3) * F_SZ;
        #pragma unroll
        for (int ks = 0; ks < 2; ks++) {
            uint32_t ah[4], al[4];
            ldsm4(ah, sb + F_AH + offA + ks * 32);
            ldsm4(al, sb + F_AL + offA + ks * 32);
            #pragma unroll
            for (int w = 0; w < 3; w++) {
                const uint32_t bw = sb + F_BB + w * 10240;
                #pragma unroll
                for (int p = 0; p < 4; p++) {
                    uint32_t bh[4], bl[4];
                    uint32_t kb = bw + offB + p * 1280 + ks * 32;
                    ldsm4(bh, kb);
                    ldsm4(bl, kb + 5120);
                    mma4(O[w][2 * p],     ah, bh[0], bh[1]);
                    mma4(O[w][2 * p],     ah, bl[0], bl[1]);
                    mma4(O[w][2 * p],     al, bh[0], bh[1]);
                    mma4(O[w][2 * p + 1], ah, bh[2], bh[3]);
                    mma4(O[w][2 * p + 1], ah, bl[2], bl[3]);
                    mma4(O[w][2 * p + 1], al, bh[2], bh[3]);
                }
            }
        }
        __syncthreads();
    }

    // ---- epilogues ----
    const int g = lane >> 2, tg = lane & 3;
    const int row0 = mb * 128 + warp * 16 + g, row1 = row0 + 8;
    const int z = row0 >> 11, n0 = row0 & (NTOK - 1), n1 = row1 & (NTOK - 1);
    const int zh = z * HEADS + h;
    const size_t baseT = (size_t)zh * DK * NTOK;

    #pragma unroll
    for (int nt = 0; nt < 8; nt++) {
        int col = nt * 8 + 2 * tg;
        uint32_t hh, ll;

        // Q: scaled + split, [zh][n][dk]
        {
            float b0 = qbias[h * DK + col], b1 = qbias[h * DK + col + 1];
            size_t i0 = ((size_t)zh * NTOK + n0) * DK + col;
            size_t i1 = ((size_t)zh * NTOK + n1) * DK + col;
            split2((O[0][nt][0] + b0) * SCALE, (O[0][nt][1] + b1) * SCALE, hh, ll);
            *(uint32_t*)&Qh_o[i0] = hh; *(uint32_t*)&Ql_o[i0] = ll;
            split2((O[0][nt][2] + b0) * SCALE, (O[0][nt][3] + b1) * SCALE, hh, ll);
            *(uint32_t*)&Qh_o[i1] = hh; *(uint32_t*)&Ql_o[i1] = ll;
        }
        // K: split, [zh][key][dk]
        {
            float b0 = kbias[h * DK + col], b1 = kbias[h * DK + col + 1];
            size_t i0 = ((size_t)zh * NTOK + n0) * DK + col;
            size_t i1 = ((size_t)zh * NTOK + n1) * DK + col;
            split2(O[1][nt][0] + b0, O[1][nt][1] + b1, hh, ll);
            *(uint32_t*)&Kh_o[i0] = hh; *(uint32_t*)&Kl_o[i0] = ll;
            split2(O[1][nt][2] + b0, O[1][nt][3] + b1, hh, ll);
            *(uint32_t*)&Kh_o[i1] = hh; *(uint32_t*)&Kl_o[i1] = ll;
        }
        // V: split + transposed, [zh][dk][key]
        {
            float b0 = vbias[h * DK + col], b1 = vbias[h * DK + col + 1];
            #pragma unroll
            for (int j = 0; j < 2; j++) {
                float v0 = O[2][nt][j]     + (j ? b1 : b0);
                float v1 = O[2][nt][2 + j] + (j ? b1 : b0);
                __nv_bfloat16 bh_, bl_;
                split1(v0, bh_, bl_);
                Vth_o[baseT + (size_t)(col + j) * NTOK + n0] = bh_;
                Vtl_o[baseT + (size_t)(col + j) * NTOK + n0] = bl_;
                split1(v1, bh_, bl_);
                Vth_o[baseT + (size_t)(col + j) * NTOK + n1] = bh_;
                Vtl_o[baseT + (size_t)(col + j) * NTOK + n1] = bl_;
            }
        }
    }
}

// ---------------------------------------------------------------------------
// bf16x3 MMA GEMM core (out-proj): 128x64 tile, K chunks of 32, 2-stage
// cp.async, ldmatrix frags. 256 threads = 8 warps.
// ---------------------------------------------------------------------------
#define G_AH      0
#define G_AL      10240
#define G_BH      20480
#define G_BL      25600
#define G_STAGE   30720

__device__ __forceinline__ void gemm_bf3_core(
    const __nv_bfloat16* __restrict__ Ahb, const __nv_bfloat16* __restrict__ Alb,
    const __nv_bfloat16* __restrict__ Bhb, const __nv_bfloat16* __restrict__ Blb,
    float O[8][4])
{
    const int tid  = threadIdx.x;
    const int warp = tid >> 5;
    const int lane = tid & 31;
    const uint32_t sbase = (uint32_t)__cvta_generic_to_shared(smem_dyn);

    const int rA = lane & 15, cA = (lane & 16) >> 1;
    const int rB = (lane & 7) | ((lane & 16) >> 1), cB = lane & 8;
    const uint32_t offA = (uint32_t)(((warp * 16 + rA) * 40 + cA) * 2);
    const uint32_t offB = (uint32_t)((rB * 40 + cB) * 2);

    const int ar0 = tid >> 2, ac = (tid & 3);
    const int ar1 = (tid + 256) >> 2;
    const int br  = tid >> 2;

    auto issue = [&](int kcid, int stage) {
        const uint32_t sb = sbase + stage * G_STAGE;
        const int kc = kcid * 32;
        cp_async16(sb + G_AH + ar0 * 80 + ac * 16, Ahb + (size_t)ar0 * DMODEL + kc + ac * 8);
        cp_async16(sb + G_AL + ar0 * 80 + ac * 16, Alb + (size_t)ar0 * DMODEL + kc + ac * 8);
        cp_async16(sb + G_AH + ar1 * 80 + ac * 16, Ahb + (size_t)ar1 * DMODEL + kc + ac * 8);
        cp_async16(sb + G_AL + ar1 * 80 + ac * 16, Alb + (size_t)ar1 * DMODEL + kc + ac * 8);
        cp_async16(sb + G_BH + br * 80 + ac * 16,  Bhb + (size_t)br * DMODEL + kc + ac * 8);
        cp_async16(sb + G_BL + br * 80 + ac * 16,  Blb + (size_t)br * DMODEL + kc + ac * 8);
    };

    issue(0, 0);
    cp_commit();

    for (int i = 0; i < 32; i++) {
        if (i + 1 < 32) {
            issue(i + 1, (i + 1) & 1);
            cp_commit();
            cp_wait<1>();
        } else {
            cp_wait<0>();
        }
        __syncthreads();

        const uint32_t sb = sbase + (i & 1) * G_STAGE;
        #pragma unroll
        for (int ks = 0; ks < 2; ks++) {
            uint32_t ah[4], al[4];
            ldsm4(ah, sb + G_AH + offA + ks * 32);
            ldsm4(al, sb + G_AL + offA + ks * 32);
            #pragma unroll
            for (int p = 0; p < 4; p++) {
                uint32_t bh[4], bl[4];
                uint32_t kb = sb + offB + p * 1280 + ks * 32;
                ldsm4(bh, kb + G_BH);
                ldsm4(bl, kb + G_BL);
                mma4(O[2 * p],     ah, bh[0], bh[1]);
                mma4(O[2 * p],     ah, bl[0], bl[1]);
                mma4(O[2 * p],     al, bh[0], bh[1]);
                mma4(O[2 * p + 1], ah, bh[2], bh[3]);
                mma4(O[2 * p + 1], ah, bl[2], bl[3]);
                mma4(O[2 * p + 1], al, bh[2], bh[3]);
            }
        }
        __syncthreads();
    }
}

// Out-proj GEMM (reads split ctx, writes fp32 out)
__global__ __launch_bounds__(256) void gemm_bf3_out(
    const __nv_bfloat16* __restrict__ Ah, const __nv_bfloat16* __restrict__ Al,
    const __nv_bfloat16* __restrict__ Bh, const __nv_bfloat16* __restrict__ Bl,
    float* __restrict__ Out)
{
    const int cb = blockIdx.x;
    const int mb = blockIdx.y;
    float O[8][4] = {};
    gemm_bf3_core(Ah + (size_t)mb * 128 * DMODEL, Al + (size_t)mb * 128 * DMODEL,
                  Bh + (size_t)cb * 64 * DMODEL,  Bl + (size_t)cb * 64 * DMODEL, O);

    const int warp = threadIdx.x >> 5, lane = threadIdx.x & 31;
    const int g = lane >> 2, tg = lane & 3;
    const int row0 = mb * 128 + warp * 16 + g, row1 = row0 + 8;

    #pragma unroll
    for (int nt = 0; nt < 8; nt++) {
        int col = cb * 64 + nt * 8 + 2 * tg;
        *(float2*)&Out[(size_t)row0 * DMODEL + col] = make_float2(O[nt][0], O[nt][1]);
        *(float2*)&Out[(size_t)row1 * DMODEL + col] = make_float2(O[nt][2], O[nt][3]);
    }
}

// ---------------------------------------------------------------------------
// Flash attention: bf16x3 MMA + cp.async 2-stage pipeline + ldmatrix frags.
// (round-9 proven version) Block = 128 threads, grid = (NTOK/64, ZH)
// ---------------------------------------------------------------------------
#define TILE_B      9216        // 64 * 72 * 2
#define STAGE_B     37120       // 4*TILE_B + 256
#define OFF_KH      0
#define OFF_KL      (TILE_B)
#define OFF_VH      (2 * TILE_B)
#define OFF_VL      (3 * TILE_B)
#define OFF_MK      (4 * TILE_B)

__global__ __launch_bounds__(128) void attn_mma(
    const __nv_bfloat16* __restrict__ Qh_g, const __nv_bfloat16* __restrict__ Ql_g,
    const __nv_bfloat16* __restrict__ Kh_g, const __nv_bfloat16* __restrict__ Kl_g,
    const __nv_bfloat16* __restrict__ Vth_g, const __nv_bfloat16* __restrict__ Vtl_g,
    const int* __restrict__ mask,
    __nv_bfloat16* __restrict__ Ch, __nv_bfloat16* __restrict__ Cl)
{
    const int qt   = blockIdx.x;
    const int zh   = blockIdx.y;
    const int z    = zh >> 4;
    const int h    = zh & 15;
    const int tid  = threadIdx.x;
    const int warp = tid >> 5;
    const int lane = tid & 31;
    const int g    = lane >> 2;
    const int tg   = lane & 3;

    typedef __nv_bfloat16(*tile_t)[72];
    const size_t base  = (size_t)zh * NTOK * DK;
    const size_t baseT = (size_t)zh * DK * NTOK;
    const uint32_t smem_u32 = (uint32_t)__cvta_generic_to_shared(smem_dyn);

    const int rA = lane & 15, cA = (lane & 16) >> 1;
    const int rB = (lane & 7) | ((lane & 16) >> 1), cB = lane & 8;
    const uint32_t offQ = (uint32_t)(((warp * 16 + rA) * 72 + cA) * 2);
    const uint32_t offF = (uint32_t)((rB * 72 + cB) * 2);

    const int lrow[4] = { tid >> 3, (tid + 128) >> 3, (tid + 256) >> 3, (tid + 384) >> 3 };
    const int lc8 = (tid & 7) * 8;

    {
        tile_t sQh = (tile_t)(smem_dyn + OFF_KH);
        tile_t sQl = (tile_t)(smem_dyn + OFF_KL);
        const __nv_bfloat16* gq_h = Qh_g + base + (size_t)qt * 64 * DK;
        const __nv_bfloat16* gq_l = Ql_g + base + (size_t)qt * 64 * DK;
        #pragma unroll
        for (int it = 0; it < 4; it++) {
            int row = lrow[it];
            *(uint4*)&sQh[row][lc8] = *(const uint4*)(gq_h + (size_t)row * DK + lc8);
            *(uint4*)&sQl[row][lc8] = *(const uint4*)(gq_l + (size_t)row * DK + lc8);
        }
    }
    __syncthreads();

    uint32_t Qh[4][4], Ql[4][4];
    #pragma unroll
    for (int kk = 0; kk < 4; kk++) {
        ldsm4(Qh[kk], smem_u32 + OFF_KH + offQ + kk * 32);
        ldsm4(Ql[kk], smem_u32 + OFF_KL + offQ + kk * 32);
    }
    __syncthreads();

    auto issue_tile = [&](int kt, int stage) {
        const uint32_t sb = smem_u32 + stage * STAGE_B;
        const __nv_bfloat16* gkh = Kh_g + base + (size_t)kt * 64 * DK;
        const __nv_bfloat16* gkl = Kl_g + base + (size_t)kt * 64 * DK;
        const __nv_bfloat16* gvh = Vth_g + baseT + kt * 64;
        const __nv_bfloat16* gvl = Vtl_g + baseT + kt * 64;
        #pragma unroll
        for (int it = 0; it < 4; it++) {
            int row = lrow[it];
            uint32_t rowoff = row * 144 + lc8 * 2;
            cp_async16(sb + OFF_KH + rowoff, gkh + (size_t)row * DK + lc8);
            cp_async16(sb + OFF_KL + rowoff, gkl + (size_t)row * DK + lc8);
            cp_async16(sb + OFF_VH + rowoff, gvh + (size_t)row * NTOK + lc8);
            cp_async16(sb + OFF_VL + rowoff, gvl + (size_t)row * NTOK + lc8);
        }
        if (tid < 64)
            cp_async4(sb + OFF_MK + tid * 4, mask + z * NTOK + kt * 64 + tid);
    };

    float O[8][4];
    #pragma unroll
    for (int nt = 0; nt < 8; nt++)
        O[nt][0] = O[nt][1] = O[nt][2] = O[nt][3] = 0.f;
    float m0 = -1e30f, m1 = -1e30f, l0 = 0.f, l1 = 0.f;

    issue_tile(0, 0);
    cp_commit();

    for (int kt = 0; kt < NTOK / 64; kt++) {
        const int cur = kt & 1;
        if (kt + 1 < NTOK / 64) {
            issue_tile(kt + 1, cur ^ 1);
            cp_commit();
            cp_wait<1>();
        } else {
            cp_wait<0>();
        }
        __syncthreads();

        const uint32_t sb = smem_u32 + cur * STAGE_B;
        int* smk = (int*)(smem_dyn + cur * STAGE_B + OFF_MK);

        float S[8][4];
        #pragma unroll
        for (int p = 0; p < 4; p++) {
            S[2*p][0] = S[2*p][1] = S[2*p][2] = S[2*p][3] = 0.f;
            S[2*p+1][0] = S[2*p+1][1] = S[2*p+1][2] = S[2*p+1][3] = 0.f;
            #pragma unroll
            for (int kk = 0; kk < 4; kk++) {
                uint32_t bh[4], bl[4];
                uint32_t kbb = sb + offF + p * 2304 + kk * 32;
                ldsm4(bh, kbb + OFF_KH);
                ldsm4(bl, kbb + OFF_KL);
                mma4(S[2*p],     Qh[kk], bh[0], bh[1]);
                mma4(S[2*p],     Qh[kk], bl[0], bl[1]);
                mma4(S[2*p],     Ql[kk], bh[0], bh[1]);
                mma4(S[2*p+1],   Qh[kk], bh[2], bh[3]);
                mma4(S[2*p+1],   Qh[kk], bl[2], bl[3]);
                mma4(S[2*p+1],   Ql[kk], bh[2], bh[3]);
            }
        }

        float mx0 = -1e30f, mx1 = -1e30f;
        #pragma unroll
        for (int nt = 0; nt < 8; nt++) {
            #pragma unroll
            for (int j = 0; j < 2; j++) {
                int key = nt * 8 + 2 * tg + j;
                bool ok = smk[key] != 0;
                float v0 = ok ? S[nt][j]     : -1e9f;
                float v1 = ok ? S[nt][2 + j] : -1e9f;
                S[nt][j] = v0; S[nt][2 + j] = v1;
                mx0 = fmaxf(mx0, v0); mx1 = fmaxf(mx1, v1);
            }
        }
        mx0 = fmaxf(mx0, __shfl_xor_sync(0xffffffffu, mx0, 1));
        mx0 = fmaxf(mx0, __shfl_xor_sync(0xffffffffu, mx0, 2));
        mx1 = fmaxf(mx1, __shfl_xor_sync(0xffffffffu, mx1, 1));
        mx1 = fmaxf(mx1, __shfl_xor_sync(0xffffffffu, mx1, 2));

        float mn0 = fmaxf(m0, mx0), mn1 = fmaxf(m1, mx1);
        float corr0 = __expf(m0 - mn0), corr1 = __expf(m1 - mn1);
        m0 = mn0; m1 = mn1;

        float ls0 = 0.f, ls1 = 0.f;
        #pragma unroll
        for (int nt = 0; nt < 8; nt++) {
            S[nt][0] = __expf(S[nt][0] - m0); ls0 += S[nt][0];
            S[nt][1] = __expf(S[nt][1] - m0); ls0 += S[nt][1];
            S[nt][2] = __expf(S[nt][2] - m1); ls1 += S[nt][2];
            S[nt][3] = __expf(S[nt][3] - m1); ls1 += S[nt][3];
        }
        ls0 += __shfl_xor_sync(0xffffffffu, ls0, 1);
        ls0 += __shfl_xor_sync(0xffffffffu, ls0, 2);
        ls1 += __shfl_xor_sync(0xffffffffu, ls1, 1);
        ls1 += __shfl_xor_sync(0xffffffffu, ls1, 2);
        l0 = l0 * corr0 + ls0;
        l1 = l1 * corr1 + ls1;

        #pragma unroll
        for (int nt = 0; nt < 8; nt++) {
            O[nt][0] *= corr0; O[nt][1] *= corr0;
            O[nt][2] *= corr1; O[nt][3] *= corr1;
        }

        #pragma unroll
        for (int kk = 0; kk < 4; kk++) {
            uint32_t ah[4], al[4];
            split2(S[2 * kk][0],     S[2 * kk][1],     ah[0], al[0]);
            split2(S[2 * kk][2],     S[2 * kk][3],     ah[1], al[1]);
            split2(S[2 * kk + 1][0], S[2 * kk + 1][1], ah[2], al[2]);
            split2(S[2 * kk + 1][2], S[2 * kk + 1][3], ah[3], al[3]);
            #pragma unroll
            for (int p = 0; p < 4; p++) {
                uint32_t bh[4], bl[4];
                uint32_t vbb = sb + offF + p * 2304 + kk * 32;
                ldsm4(bh, vbb + OFF_VH);
                ldsm4(bl, vbb + OFF_VL);
                mma4(O[2*p],     ah, bh[0], bh[1]);
                mma4(O[2*p],     ah, bl[0], bl[1]);
                mma4(O[2*p],     al, bh[0], bh[1]);
                mma4(O[2*p+1],   ah, bh[2], bh[3]);
                mma4(O[2*p+1],   ah, bl[2], bl[3]);
                mma4(O[2*p+1],   al, bh[2], bh[3]);
            }
        }
        __syncthreads();
    }

    const int tok0 = qt * 64 + warp * 16 + g;
    const int tok1 = tok0 + 8;
    const int qv0 = mask[z * NTOK + tok0];
    const int qv1 = mask[z * NTOK + tok1];
    const float inv0 = (qv0 && l0 > 0.f) ? 1.0f / l0 : 0.f;
    const float inv1 = (qv1 && l1 > 0.f) ? 1.0f / l1 : 0.f;

    #pragma unroll
    for (int nt = 0; nt < 8; nt++) {
        int dk = nt * 8 + 2 * tg;
        size_t i0 = ((size_t)(z * NTOK + tok0)) * DMODEL + h * DK + dk;
        size_t i1 = ((size_t)(z * NTOK + tok1)) * DMODEL + h * DK + dk;
        uint32_t hh, ll;
        split2(O[nt][0] * inv0, O[nt][1] * inv0, hh, ll);
        *(uint32_t*)&Ch[i0] = hh; *(uint32_t*)&Cl[i0] = ll;
        split2(O[nt][2] * inv1, O[nt][3] * inv1, hh, ll);
        *(uint32_t*)&Ch[i1] = hh; *(uint32_t*)&Cl[i1] = ll;
    }
}

// ---------------------------------------------------------------------------
// Host entry
// ---------------------------------------------------------------------------
extern "C" void kernel_launch(void* const* d_in, const int* in_sizes, int n_in,
                              void* d_out, int out_size)
{
    const float* x     = (const float*)d_in[0];
    const int*   mask  = (const int*)  d_in[1];
    const float* qproj = (const float*)d_in[2];
    const float* kproj = (const float*)d_in[3];
    const float* vproj = (const float*)d_in[4];
    const float* qbias = (const float*)d_in[5];
    const float* kbias = (const float*)d_in[6];
    const float* vbias = (const float*)d_in[7];
    const float* outw  = (const float*)d_in[8];
    float* out = (float*)d_out;

    __nv_bfloat16 *Xh, *Xl, *BQh, *BQl, *BKh, *BKl, *BVh, *BVl, *Wh, *Wl;
    __nv_bfloat16 *Ch, *Cl, *Qh, *Ql, *Kh, *Kl, *Vth, *Vtl;
    cudaGetSymbolAddress((void**)&Xh,  g_Xh);
    cudaGetSymbolAddress((void**)&Xl,  g_Xl);
    cudaGetSymbolAddress((void**)&BQh, g_BQh);
    cudaGetSymbolAddress((void**)&BQl, g_BQl);
    cudaGetSymbolAddress((void**)&BKh, g_BKh);
    cudaGetSymbolAddress((void**)&BKl, g_BKl);
    cudaGetSymbolAddress((void**)&BVh, g_BVh);
    cudaGetSymbolAddress((void**)&BVl, g_BVl);
    cudaGetSymbolAddress((void**)&Wh,  g_Wh);
    cudaGetSymbolAddress((void**)&Wl,  g_Wl);
    cudaGetSymbolAddress((void**)&Ch,  g_Ch);
    cudaGetSymbolAddress((void**)&Cl,  g_Cl);
    cudaGetSymbolAddress((void**)&Qh,  g_Qh);
    cudaGetSymbolAddress((void**)&Ql,  g_Ql);
    cudaGetSymbolAddress((void**)&Kh,  g_Kh);
    cudaGetSymbolAddress((void**)&Kl,  g_Kl);
    cudaGetSymbolAddress((void**)&Vth, g_Vth);
    cudaGetSymbolAddress((void**)&Vtl, g_Vtl);

    static bool attr_set = false;
    if (!attr_set) {
        cudaFuncSetAttribute(attn_mma,
                             cudaFuncAttributeMaxDynamicSharedMemorySize, 2 * STAGE_B);
        cudaFuncSetAttribute(gemm_bf3_qkv_fused,
                             cudaFuncAttributeMaxDynamicSharedMemorySize, F_SMEM);
        cudaFuncSetAttribute(gemm_bf3_out,
                             cudaFuncAttributeMaxDynamicSharedMemorySize, 2 * G_STAGE);
        attr_set = true;
    }

    // input splits
    split_any4_kernel<<<1024, 256>>>((const float4*)x, (uint2*)Xh, (uint2*)Xl,
                                     ROWS * DMODEL / 4);
    split_proj3_kernel<<<dim3(DMODEL / 64, HEADS, 3), 256>>>(
        qproj, kproj, vproj, BQh, BQl, BKh, BKl, BVh, BVl);
    split_any4_kernel<<<512, 256>>>((const float4*)outw, (uint2*)Wh, (uint2*)Wl,
                                    DMODEL * DMODEL / 4);

    // fused QKV projection (tensor-core, 3-stage pipeline, split epilogues)
    gemm_bf3_qkv_fused<<<dim3(HEADS, ROWS / 128), 256, F_SMEM>>>(
        Xh, Xl, BQh, BQl, BKh, BKl, BVh, BVl,
        qbias, kbias, vbias, Qh, Ql, Kh, Kl, Vth, Vtl);

    // attention (mma.sync, cp.async pipelined, LDSM frags)
    attn_mma<<<dim3(NTOK / 64, ZH), 128, 2 * STAGE_B>>>(
        Qh, Ql, Kh, Kl, Vth, Vtl, mask, Ch, Cl);

    // output projection
    gemm_bf3_out<<<dim3(DMODEL / 64, ROWS / 128), 256, 2 * G_STAGE>>>(
        Ch, Cl, Wh, Wl, out);
}

// round 15
// speedup vs baseline: 1.0927x; 1.0361x over previous
#include <cuda_runtime.h>
#include <cuda_bf16.h>
#include <cstdint>

// Problem constants
#define ZB     2
#define NTOK   2048
#define DMODEL 1024
#define HEADS  16
#define DK     64
#define ROWS   (ZB * NTOK)          // 4096
#define SCALE  0.125f               // DK^-0.5
#define ZH     (ZB * HEADS)         // 32

// ---------------------------------------------------------------------------
// Device scratch (no runtime allocation allowed)
// ---------------------------------------------------------------------------
__device__ __nv_bfloat16 g_Xh[ROWS * DMODEL];   // x split
__device__ __nv_bfloat16 g_Xl[ROWS * DMODEL];
__device__ __nv_bfloat16 g_BQh[HEADS * DK * DMODEL];  // proj split, [h][n][k]
__device__ __nv_bfloat16 g_BQl[HEADS * DK * DMODEL];
__device__ __nv_bfloat16 g_BKh[HEADS * DK * DMODEL];
__device__ __nv_bfloat16 g_BKl[HEADS * DK * DMODEL];
__device__ __nv_bfloat16 g_BVh[HEADS * DK * DMODEL];
__device__ __nv_bfloat16 g_BVl[HEADS * DK * DMODEL];
__device__ __nv_bfloat16 g_Wh[DMODEL * DMODEL]; // out_w split ([n][k] = native)
__device__ __nv_bfloat16 g_Wl[DMODEL * DMODEL];
__device__ __nv_bfloat16 g_Ch[ROWS * DMODEL];   // ctx split (attention output)
__device__ __nv_bfloat16 g_Cl[ROWS * DMODEL];

// pre-split QKV (written directly by GEMM epilogues)
__device__ __nv_bfloat16 g_Qh[ZH * NTOK * DK];  // [zh][n][dk], SCALE folded
__device__ __nv_bfloat16 g_Ql[ZH * NTOK * DK];
__device__ __nv_bfloat16 g_Kh[ZH * NTOK * DK];  // [zh][key][dk]
__device__ __nv_bfloat16 g_Kl[ZH * NTOK * DK];
__device__ __nv_bfloat16 g_Vth[ZH * DK * NTOK]; // transposed: [zh][dk][key]
__device__ __nv_bfloat16 g_Vtl[ZH * DK * NTOK];

extern __shared__ unsigned char smem_dyn[];

// ---------------------------------------------------------------------------
// helpers
// ---------------------------------------------------------------------------
__device__ __forceinline__ uint32_t packb(__nv_bfloat16 x, __nv_bfloat16 y) {
    return (uint32_t)__bfloat16_as_ushort(x) |
           ((uint32_t)__bfloat16_as_ushort(y) << 16);
}
__device__ __forceinline__ void split1(float x, __nv_bfloat16& h, __nv_bfloat16& l) {
    h = __float2bfloat16(x);
    l = __float2bfloat16(x - __bfloat162float(h));
}
__device__ __forceinline__ void split2(float x, float y, uint32_t& hi, uint32_t& lo) {
    __nv_bfloat16 xh, xl, yh, yl;
    split1(x, xh, xl);
    split1(y, yh, yl);
    hi = packb(xh, yh);
    lo = packb(xl, yl);
}

__device__ __forceinline__ void mma4(float* C, const uint32_t* a,
                                     uint32_t b0, uint32_t b1)
{
    asm volatile(
        "mma.sync.aligned.m16n8k16.row.col.f32.bf16.bf16.f32 "
        "{%0,%1,%2,%3},{%4,%5,%6,%7},{%8,%9},{%0,%1,%2,%3};\n"
        : "+f"(C[0]), "+f"(C[1]), "+f"(C[2]), "+f"(C[3])
        : "r"(a[0]), "r"(a[1]), "r"(a[2]), "r"(a[3]), "r"(b0), "r"(b1));
}

__device__ __forceinline__ void ldsm4(uint32_t* r, uint32_t addr) {
    asm volatile("ldmatrix.sync.aligned.m8n8.x4.shared.b16 {%0,%1,%2,%3}, [%4];"
                 : "=r"(r[0]), "=r"(r[1]), "=r"(r[2]), "=r"(r[3]) : "r"(addr));
}

__device__ __forceinline__ void cp_async16(uint32_t dst, const void* src) {
    asm volatile("cp.async.cg.shared.global [%0], [%1], 16;" :: "r"(dst), "l"(src));
}
__device__ __forceinline__ void cp_async4(uint32_t dst, const void* src) {
    asm volatile("cp.async.ca.shared.global [%0], [%1], 4;" :: "r"(dst), "l"(src));
}
__device__ __forceinline__ void cp_commit() {
    asm volatile("cp.async.commit_group;");
}
template <int N>
__device__ __forceinline__ void cp_wait() {
    asm volatile("cp.async.wait_group %0;" :: "n"(N));
}

// ---------------------------------------------------------------------------
// Vectorized elementwise split: fp32 -> (hi, lo) bf16
// ---------------------------------------------------------------------------
__global__ void split_any4_kernel(const float4* __restrict__ in,
                                  uint2* __restrict__ hi,
                                  uint2* __restrict__ lo, int n4)
{
    for (int i = blockIdx.x * blockDim.x + threadIdx.x; i < n4;
         i += gridDim.x * blockDim.x) {
        float4 v = in[i];
        uint32_t h0, l0, h1, l1;
        split2(v.x, v.y, h0, l0);
        split2(v.z, v.w, h1, l1);
        hi[i] = make_uint2(h0, h1);
        lo[i] = make_uint2(l0, l1);
    }
}

// ---------------------------------------------------------------------------
// Proj split + transpose for Q,K,V in one launch (blockIdx.z selects).
// proj[h][d][n] (fp32) -> B[h][n][d] hi/lo (bf16). grid=(16, HEADS, 3)
// ---------------------------------------------------------------------------
__global__ __launch_bounds__(256) void split_proj3_kernel(
    const float* __restrict__ pq, const float* __restrict__ pk,
    const float* __restrict__ pv,
    __nv_bfloat16* __restrict__ qh, __nv_bfloat16* __restrict__ ql,
    __nv_bfloat16* __restrict__ kh, __nv_bfloat16* __restrict__ kl,
    __nv_bfloat16* __restrict__ vh, __nv_bfloat16* __restrict__ vl)
{
    const int dt = blockIdx.x;
    const int h  = blockIdx.y;
    const int w  = blockIdx.z;
    const float* proj = (w == 0) ? pq : (w == 1) ? pk : pv;
    __nv_bfloat16* Bh = (w == 0) ? qh : (w == 1) ? kh : vh;
    __nv_bfloat16* Bl = (w == 0) ? ql : (w == 1) ? kl : vl;

    const int tid = threadIdx.x;
    __shared__ float tile[64][65];

    const float* src = proj + ((size_t)h * DMODEL + dt * 64) * DK;
    #pragma unroll
    for (int it = 0; it < 4; it++) {
        int i4 = tid + it * 256;
        int r  = i4 >> 4;
        int c4 = (i4 & 15) * 4;
        float4 v = *(const float4*)(src + (size_t)r * DK + c4);
        tile[r][c4 + 0] = v.x; tile[r][c4 + 1] = v.y;
        tile[r][c4 + 2] = v.z; tile[r][c4 + 3] = v.w;
    }
    __syncthreads();
    #pragma unroll
    for (int it = 0; it < 16; it++) {
        int o = tid + it * 256;
        int n = o >> 6;
        int j = o & 63;
        float x = tile[j][n];
        __nv_bfloat16 hh, ll;
        split1(x, hh, ll);
        size_t idx = ((size_t)h * DK + n) * DMODEL + dt * 64 + j;
        Bh[idx] = hh;
        Bl[idx] = ll;
    }
}

// ---------------------------------------------------------------------------
// FUSED QKV bf16x3 MMA GEMM, occupancy-tuned: 64-row x 64-col x 3-output tile.
// 8 warps = 4 row-groups (16 rows) x 2 col-halves (32 cols); A staged once.
// 2-stage cp.async, 40960 B/stage -> 81920 B SMEM -> 2 CTAs/SM.
// __launch_bounds__(256, 2) caps regs at 128 (48 accum floats/thread).
// grid = (HEADS, ROWS/64)
// ---------------------------------------------------------------------------
#define F2_AH    0
#define F2_AL    5120
#define F2_B     10240      // + w*10240 (hi), +5120 (lo)
#define F2_SZ    40960
#define F2_SMEM  (2 * F2_SZ)   // 81920

__global__ __launch_bounds__(256, 2) void gemm_bf3_qkv_fused(
    const __nv_bfloat16* __restrict__ Xh, const __nv_bfloat16* __restrict__ Xl,
    const __nv_bfloat16* __restrict__ BQh, const __nv_bfloat16* __restrict__ BQl,
    const __nv_bfloat16* __restrict__ BKh, const __nv_bfloat16* __restrict__ BKl,
    const __nv_bfloat16* __restrict__ BVh, const __nv_bfloat16* __restrict__ BVl,
    const float* __restrict__ qbias, const float* __restrict__ kbias,
    const float* __restrict__ vbias,
    __nv_bfloat16* __restrict__ Qh_o, __nv_bfloat16* __restrict__ Ql_o,
    __nv_bfloat16* __restrict__ Kh_o, __nv_bfloat16* __restrict__ Kl_o,
    __nv_bfloat16* __restrict__ Vth_o, __nv_bfloat16* __restrict__ Vtl_o)
{
    const int h  = blockIdx.x;
    const int mb = blockIdx.y;
    const int tid  = threadIdx.x;
    const int warp = tid >> 5;
    const int lane = tid & 31;
    const int warpRow = warp & 3;       // 16-row group
    const int warpCol = warp >> 2;      // 32-col half
    const uint32_t sbase = (uint32_t)__cvta_generic_to_shared(smem_dyn);

    const __nv_bfloat16* Ahb = Xh + (size_t)mb * 64 * DMODEL;
    const __nv_bfloat16* Alb = Xl + (size_t)mb * 64 * DMODEL;
    const __nv_bfloat16* Bh_[3] = { BQh + (size_t)h * DK * DMODEL,
                                    BKh + (size_t)h * DK * DMODEL,
                                    BVh + (size_t)h * DK * DMODEL };
    const __nv_bfloat16* Bl_[3] = { BQl + (size_t)h * DK * DMODEL,
                                    BKl + (size_t)h * DK * DMODEL,
                                    BVl + (size_t)h * DK * DMODEL };

    // LDSM per-lane offsets (stride 40 elems = 80 B rows)
    const int rA = lane & 15, cAo = (lane & 16) >> 1;
    const int rB = (lane & 7) | ((lane & 16) >> 1), cBo = lane & 8;
    const uint32_t offA = (uint32_t)(((warpRow * 16 + rA) * 40 + cAo) * 2);
    const uint32_t offB = (uint32_t)((rB * 40 + cBo) * 2);

    // cp.async coordinates: each thread owns one 16B seg per 64x32 array
    const int cr = tid >> 2;            // row 0..63
    const int cs = tid & 3;             // seg 0..3
    const uint32_t so = (uint32_t)(cr * 80 + cs * 16);

    auto issue = [&](int kcid, int stage) {
        const uint32_t sb = sbase + stage * F2_SZ;
        const size_t go = (size_t)cr * DMODEL + kcid * 32 + cs * 8;
        cp_async16(sb + F2_AH + so, Ahb + go);
        cp_async16(sb + F2_AL + so, Alb + go);
        #pragma unroll
        for (int w = 0; w < 3; w++) {
            const uint32_t bw = sb + F2_B + w * 10240;
            cp_async16(bw + so,        Bh_[w] + go);
            cp_async16(bw + 5120 + so, Bl_[w] + go);
        }
    };

    float O[3][4][4];
    #pragma unroll
    for (int w = 0; w < 3; w++)
        #pragma unroll
        for (int nt = 0; nt < 4; nt++)
            O[w][nt][0] = O[w][nt][1] = O[w][nt][2] = O[w][nt][3] = 0.f;

    issue(0, 0); cp_commit();

    for (int i = 0; i < 32; i++) {
        if (i + 1 < 32) {
            issue(i + 1, (i + 1) & 1);
            cp_commit();
            cp_wait<1>();
        } else {
            cp_wait<0>();
        }
        __syncthreads();

        const uint32_t sb = sbase + (i & 1) * F2_SZ;
        #pragma unroll
        for (int ks = 0; ks < 2; ks++) {
            uint32_t ah[4], al[4];
            ldsm4(ah, sb + F2_AH + offA + ks * 32);
            ldsm4(al, sb + F2_AL + offA + ks * 32);
            #pragma unroll
            for (int w = 0; w < 3; w++) {
                const uint32_t bw = sb + F2_B + w * 10240;
                #pragma unroll
                for (int p = 0; p < 2; p++) {
                    uint32_t bh[4], bl[4];
                    uint32_t kb = bw + offB + (warpCol * 32 + p * 16) * 80 + ks * 32;
                    ldsm4(bh, kb);
                    ldsm4(bl, kb + 5120);
                    mma4(O[w][2 * p],     ah, bh[0], bh[1]);
                    mma4(O[w][2 * p],     ah, bl[0], bl[1]);
                    mma4(O[w][2 * p],     al, bh[0], bh[1]);
                    mma4(O[w][2 * p + 1], ah, bh[2], bh[3]);
                    mma4(O[w][2 * p + 1], ah, bl[2], bl[3]);
                    mma4(O[w][2 * p + 1], al, bh[2], bh[3]);
                }
            }
        }
        __syncthreads();
    }

    // ---- epilogues ----
    const int g = lane >> 2, tg = lane & 3;
    const int row0 = mb * 64 + warpRow * 16 + g, row1 = row0 + 8;
    const int z = row0 >> 11, n0 = row0 & (NTOK - 1), n1 = row1 & (NTOK - 1);
    const int zh = z * HEADS + h;
    const size_t baseT = (size_t)zh * DK * NTOK;

    #pragma unroll
    for (int nt = 0; nt < 4; nt++) {
        int col = warpCol * 32 + nt * 8 + 2 * tg;
        uint32_t hh, ll;

        // Q: scaled + split, [zh][n][dk]
        {
            float b0 = qbias[h * DK + col], b1 = qbias[h * DK + col + 1];
            size_t i0 = ((size_t)zh * NTOK + n0) * DK + col;
            size_t i1 = ((size_t)zh * NTOK + n1) * DK + col;
            split2((O[0][nt][0] + b0) * SCALE, (O[0][nt][1] + b1) * SCALE, hh, ll);
            *(uint32_t*)&Qh_o[i0] = hh; *(uint32_t*)&Ql_o[i0] = ll;
            split2((O[0][nt][2] + b0) * SCALE, (O[0][nt][3] + b1) * SCALE, hh, ll);
            *(uint32_t*)&Qh_o[i1] = hh; *(uint32_t*)&Ql_o[i1] = ll;
        }
        // K: split, [zh][key][dk]
        {
            float b0 = kbias[h * DK + col], b1 = kbias[h * DK + col + 1];
            size_t i0 = ((size_t)zh * NTOK + n0) * DK + col;
            size_t i1 = ((size_t)zh * NTOK + n1) * DK + col;
            split2(O[1][nt][0] + b0, O[1][nt][1] + b1, hh, ll);
            *(uint32_t*)&Kh_o[i0] = hh; *(uint32_t*)&Kl_o[i0] = ll;
            split2(O[1][nt][2] + b0, O[1][nt][3] + b1, hh, ll);
            *(uint32_t*)&Kh_o[i1] = hh; *(uint32_t*)&Kl_o[i1] = ll;
        }
        // V: split + transposed, [zh][dk][key]
        {
            float b0 = vbias[h * DK + col], b1 = vbias[h * DK + col + 1];
            #pragma unroll
            for (int j = 0; j < 2; j++) {
                float v0 = O[2][nt][j]     + (j ? b1 : b0);
                float v1 = O[2][nt][2 + j] + (j ? b1 : b0);
                __nv_bfloat16 bh_, bl_;
                split1(v0, bh_, bl_);
                Vth_o[baseT + (size_t)(col + j) * NTOK + n0] = bh_;
                Vtl_o[baseT + (size_t)(col + j) * NTOK + n0] = bl_;
                split1(v1, bh_, bl_);
                Vth_o[baseT + (size_t)(col + j) * NTOK + n1] = bh_;
                Vtl_o[baseT + (size_t)(col + j) * NTOK + n1] = bl_;
            }
        }
    }
}

// ---------------------------------------------------------------------------
// bf16x3 MMA GEMM core (out-proj): 128x64 tile, K chunks of 32, 2-stage
// cp.async, ldmatrix frags. 256 threads = 8 warps.
// ---------------------------------------------------------------------------
#define G_AH      0
#define G_AL      10240
#define G_BH      20480
#define G_BL      25600
#define G_STAGE   30720

__device__ __forceinline__ void gemm_bf3_core(
    const __nv_bfloat16* __restrict__ Ahb, const __nv_bfloat16* __restrict__ Alb,
    const __nv_bfloat16* __restrict__ Bhb, const __nv_bfloat16* __restrict__ Blb,
    float O[8][4])
{
    const int tid  = threadIdx.x;
    const int warp = tid >> 5;
    const int lane = tid & 31;
    const uint32_t sbase = (uint32_t)__cvta_generic_to_shared(smem_dyn);

    const int rA = lane & 15, cA = (lane & 16) >> 1;
    const int rB = (lane & 7) | ((lane & 16) >> 1), cB = lane & 8;
    const uint32_t offA = (uint32_t)(((warp * 16 + rA) * 40 + cA) * 2);
    const uint32_t offB = (uint32_t)((rB * 40 + cB) * 2);

    const int ar0 = tid >> 2, ac = (tid & 3);
    const int ar1 = (tid + 256) >> 2;
    const int br  = tid >> 2;

    auto issue = [&](int kcid, int stage) {
        const uint32_t sb = sbase + stage * G_STAGE;
        const int kc = kcid * 32;
        cp_async16(sb + G_AH + ar0 * 80 + ac * 16, Ahb + (size_t)ar0 * DMODEL + kc + ac * 8);
        cp_async16(sb + G_AL + ar0 * 80 + ac * 16, Alb + (size_t)ar0 * DMODEL + kc + ac * 8);
        cp_async16(sb + G_AH + ar1 * 80 + ac * 16, Ahb + (size_t)ar1 * DMODEL + kc + ac * 8);
        cp_async16(sb + G_AL + ar1 * 80 + ac * 16, Alb + (size_t)ar1 * DMODEL + kc + ac * 8);
        cp_async16(sb + G_BH + br * 80 + ac * 16,  Bhb + (size_t)br * DMODEL + kc + ac * 8);
        cp_async16(sb + G_BL + br * 80 + ac * 16,  Blb + (size_t)br * DMODEL + kc + ac * 8);
    };

    issue(0, 0);
    cp_commit();

    for (int i = 0; i < 32; i++) {
        if (i + 1 < 32) {
            issue(i + 1, (i + 1) & 1);
            cp_commit();
            cp_wait<1>();
        } else {
            cp_wait<0>();
        }
        __syncthreads();

        const uint32_t sb = sbase + (i & 1) * G_STAGE;
        #pragma unroll
        for (int ks = 0; ks < 2; ks++) {
            uint32_t ah[4], al[4];
            ldsm4(ah, sb + G_AH + offA + ks * 32);
            ldsm4(al, sb + G_AL + offA + ks * 32);
            #pragma unroll
            for (int p = 0; p < 4; p++) {
                uint32_t bh[4], bl[4];
                uint32_t kb = sb + offB + p * 1280 + ks * 32;
                ldsm4(bh, kb + G_BH);
                ldsm4(bl, kb + G_BL);
                mma4(O[2 * p],     ah, bh[0], bh[1]);
                mma4(O[2 * p],     ah, bl[0], bl[1]);
                mma4(O[2 * p],     al, bh[0], bh[1]);
                mma4(O[2 * p + 1], ah, bh[2], bh[3]);
                mma4(O[2 * p + 1], ah, bl[2], bl[3]);
                mma4(O[2 * p + 1], al, bh[2], bh[3]);
            }
        }
        __syncthreads();
    }
}

// Out-proj GEMM (reads split ctx, writes fp32 out)
__global__ __launch_bounds__(256) void gemm_bf3_out(
    const __nv_bfloat16* __restrict__ Ah, const __nv_bfloat16* __restrict__ Al,
    const __nv_bfloat16* __restrict__ Bh, const __nv_bfloat16* __restrict__ Bl,
    float* __restrict__ Out)
{
    const int cb = blockIdx.x;
    const int mb = blockIdx.y;
    float O[8][4] = {};
    gemm_bf3_core(Ah + (size_t)mb * 128 * DMODEL, Al + (size_t)mb * 128 * DMODEL,
                  Bh + (size_t)cb * 64 * DMODEL,  Bl + (size_t)cb * 64 * DMODEL, O);

    const int warp = threadIdx.x >> 5, lane = threadIdx.x & 31;
    const int g = lane >> 2, tg = lane & 3;
    const int row0 = mb * 128 + warp * 16 + g, row1 = row0 + 8;

    #pragma unroll
    for (int nt = 0; nt < 8; nt++) {
        int col = cb * 64 + nt * 8 + 2 * tg;
        *(float2*)&Out[(size_t)row0 * DMODEL + col] = make_float2(O[nt][0], O[nt][1]);
        *(float2*)&Out[(size_t)row1 * DMODEL + col] = make_float2(O[nt][2], O[nt][3]);
    }
}

// ---------------------------------------------------------------------------
// Flash attention: bf16x3 MMA + cp.async 2-stage pipeline + ldmatrix frags.
// (round-9 proven version) Block = 128 threads, grid = (NTOK/64, ZH)
// ---------------------------------------------------------------------------
#define TILE_B      9216        // 64 * 72 * 2
#define STAGE_B     37120       // 4*TILE_B + 256
#define OFF_KH      0
#define OFF_KL      (TILE_B)
#define OFF_VH      (2 * TILE_B)
#define OFF_VL      (3 * TILE_B)
#define OFF_MK      (4 * TILE_B)

__global__ __launch_bounds__(128) void attn_mma(
    const __nv_bfloat16* __restrict__ Qh_g, const __nv_bfloat16* __restrict__ Ql_g,
    const __nv_bfloat16* __restrict__ Kh_g, const __nv_bfloat16* __restrict__ Kl_g,
    const __nv_bfloat16* __restrict__ Vth_g, const __nv_bfloat16* __restrict__ Vtl_g,
    const int* __restrict__ mask,
    __nv_bfloat16* __restrict__ Ch, __nv_bfloat16* __restrict__ Cl)
{
    const int qt   = blockIdx.x;
    const int zh   = blockIdx.y;
    const int z    = zh >> 4;
    const int h    = zh & 15;
    const int tid  = threadIdx.x;
    const int warp = tid >> 5;
    const int lane = tid & 31;
    const int g    = lane >> 2;
    const int tg   = lane & 3;

    typedef __nv_bfloat16(*tile_t)[72];
    const size_t base  = (size_t)zh * NTOK * DK;
    const size_t baseT = (size_t)zh * DK * NTOK;
    const uint32_t smem_u32 = (uint32_t)__cvta_generic_to_shared(smem_dyn);

    const int rA = lane & 15, cA = (lane & 16) >> 1;
    const int rB = (lane & 7) | ((lane & 16) >> 1), cB = lane & 8;
    const uint32_t offQ = (uint32_t)(((warp * 16 + rA) * 72 + cA) * 2);
    const uint32_t offF = (uint32_t)((rB * 72 + cB) * 2);

    const int lrow[4] = { tid >> 3, (tid + 128) >> 3, (tid + 256) >> 3, (tid + 384) >> 3 };
    const int lc8 = (tid & 7) * 8;

    {
        tile_t sQh = (tile_t)(smem_dyn + OFF_KH);
        tile_t sQl = (tile_t)(smem_dyn + OFF_KL);
        const __nv_bfloat16* gq_h = Qh_g + base + (size_t)qt * 64 * DK;
        const __nv_bfloat16* gq_l = Ql_g + base + (size_t)qt * 64 * DK;
        #pragma unroll
        for (int it = 0; it < 4; it++) {
            int row = lrow[it];
            *(uint4*)&sQh[row][lc8] = *(const uint4*)(gq_h + (size_t)row * DK + lc8);
            *(uint4*)&sQl[row][lc8] = *(const uint4*)(gq_l + (size_t)row * DK + lc8);
        }
    }
    __syncthreads();

    uint32_t Qh[4][4], Ql[4][4];
    #pragma unroll
    for (int kk = 0; kk < 4; kk++) {
        ldsm4(Qh[kk], smem_u32 + OFF_KH + offQ + kk * 32);
        ldsm4(Ql[kk], smem_u32 + OFF_KL + offQ + kk * 32);
    }
    __syncthreads();

    auto issue_tile = [&](int kt, int stage) {
        const uint32_t sb = smem_u32 + stage * STAGE_B;
        const __nv_bfloat16* gkh = Kh_g + base + (size_t)kt * 64 * DK;
        const __nv_bfloat16* gkl = Kl_g + base + (size_t)kt * 64 * DK;
        const __nv_bfloat16* gvh = Vth_g + baseT + kt * 64;
        const __nv_bfloat16* gvl = Vtl_g + baseT + kt * 64;
        #pragma unroll
        for (int it = 0; it < 4; it++) {
            int row = lrow[it];
            uint32_t rowoff = row * 144 + lc8 * 2;
            cp_async16(sb + OFF_KH + rowoff, gkh + (size_t)row * DK + lc8);
            cp_async16(sb + OFF_KL + rowoff, gkl + (size_t)row * DK + lc8);
            cp_async16(sb + OFF_VH + rowoff, gvh + (size_t)row * NTOK + lc8);
            cp_async16(sb + OFF_VL + rowoff, gvl + (size_t)row * NTOK + lc8);
        }
        if (tid < 64)
            cp_async4(sb + OFF_MK + tid * 4, mask + z * NTOK + kt * 64 + tid);
    };

    float O[8][4];
    #pragma unroll
    for (int nt = 0; nt < 8; nt++)
        O[nt][0] = O[nt][1] = O[nt][2] = O[nt][3] = 0.f;
    float m0 = -1e30f, m1 = -1e30f, l0 = 0.f, l1 = 0.f;

    issue_tile(0, 0);
    cp_commit();

    for (int kt = 0; kt < NTOK / 64; kt++) {
        const int cur = kt & 1;
        if (kt + 1 < NTOK / 64) {
            issue_tile(kt + 1, cur ^ 1);
            cp_commit();
            cp_wait<1>();
        } else {
            cp_wait<0>();
        }
        __syncthreads();

        const uint32_t sb = smem_u32 + cur * STAGE_B;
        int* smk = (int*)(smem_dyn + cur * STAGE_B + OFF_MK);

        float S[8][4];
        #pragma unroll
        for (int p = 0; p < 4; p++) {
            S[2*p][0] = S[2*p][1] = S[2*p][2] = S[2*p][3] = 0.f;
            S[2*p+1][0] = S[2*p+1][1] = S[2*p+1][2] = S[2*p+1][3] = 0.f;
            #pragma unroll
            for (int kk = 0; kk < 4; kk++) {
                uint32_t bh[4], bl[4];
                uint32_t kbb = sb + offF + p * 2304 + kk * 32;
                ldsm4(bh, kbb + OFF_KH);
                ldsm4(bl, kbb + OFF_KL);
                mma4(S[2*p],     Qh[kk], bh[0], bh[1]);
                mma4(S[2*p],     Qh[kk], bl[0], bl[1]);
                mma4(S[2*p],     Ql[kk], bh[0], bh[1]);
                mma4(S[2*p+1],   Qh[kk], bh[2], bh[3]);
                mma4(S[2*p+1],   Qh[kk], bl[2], bl[3]);
                mma4(S[2*p+1],   Ql[kk], bh[2], bh[3]);
            }
        }

        float mx0 = -1e30f, mx1 = -1e30f;
        #pragma unroll
        for (int nt = 0; nt < 8; nt++) {
            #pragma unroll
            for (int j = 0; j < 2; j++) {
                int key = nt * 8 + 2 * tg + j;
                bool ok = smk[key] != 0;
                float v0 = ok ? S[nt][j]     : -1e9f;
                float v1 = ok ? S[nt][2 + j] : -1e9f;
                S[nt][j] = v0; S[nt][2 + j] = v1;
                mx0 = fmaxf(mx0, v0); mx1 = fmaxf(mx1, v1);
            }
        }
        mx0 = fmaxf(mx0, __shfl_xor_sync(0xffffffffu, mx0, 1));
        mx0 = fmaxf(mx0, __shfl_xor_sync(0xffffffffu, mx0, 2));
        mx1 = fmaxf(mx1, __shfl_xor_sync(0xffffffffu, mx1, 1));
        mx1 = fmaxf(mx1, __shfl_xor_sync(0xffffffffu, mx1, 2));

        float mn0 = fmaxf(m0, mx0), mn1 = fmaxf(m1, mx1);
        float corr0 = __expf(m0 - mn0), corr1 = __expf(m1 - mn1);
        m0 = mn0; m1 = mn1;

        float ls0 = 0.f, ls1 = 0.f;
        #pragma unroll
        for (int nt = 0; nt < 8; nt++) {
            S[nt][0] = __expf(S[nt][0] - m0); ls0 += S[nt][0];
            S[nt][1] = __expf(S[nt][1] - m0); ls0 += S[nt][1];
            S[nt][2] = __expf(S[nt][2] - m1); ls1 += S[nt][2];
            S[nt][3] = __expf(S[nt][3] - m1); ls1 += S[nt][3];
        }
        ls0 += __shfl_xor_sync(0xffffffffu, ls0, 1);
        ls0 += __shfl_xor_sync(0xffffffffu, ls0, 2);
        ls1 += __shfl_xor_sync(0xffffffffu, ls1, 1);
        ls1 += __shfl_xor_sync(0xffffffffu, ls1, 2);
        l0 = l0 * corr0 + ls0;
        l1 = l1 * corr1 + ls1;

        #pragma unroll
        for (int nt = 0; nt < 8; nt++) {
            O[nt][0] *= corr0; O[nt][1] *= corr0;
            O[nt][2] *= corr1; O[nt][3] *= corr1;
        }

        #pragma unroll
        for (int kk = 0; kk < 4; kk++) {
            uint32_t ah[4], al[4];
            split2(S[2 * kk][0],     S[2 * kk][1],     ah[0], al[0]);
            split2(S[2 * kk][2],     S[2 * kk][3],     ah[1], al[1]);
            split2(S[2 * kk + 1][0], S[2 * kk + 1][1], ah[2], al[2]);
            split2(S[2 * kk + 1][2], S[2 * kk + 1][3], ah[3], al[3]);
            #pragma unroll
            for (int p = 0; p < 4; p++) {
                uint32_t bh[4], bl[4];
                uint32_t vbb = sb + offF + p * 2304 + kk * 32;
                ldsm4(bh, vbb + OFF_VH);
                ldsm4(bl, vbb + OFF_VL);
                mma4(O[2*p],     ah, bh[0], bh[1]);
                mma4(O[2*p],     ah, bl[0], bl[1]);
                mma4(O[2*p],     al, bh[0], bh[1]);
                mma4(O[2*p+1],   ah, bh[2], bh[3]);
                mma4(O[2*p+1],   ah, bl[2], bl[3]);
                mma4(O[2*p+1],   al, bh[2], bh[3]);
            }
        }
        __syncthreads();
    }

    const int tok0 = qt * 64 + warp * 16 + g;
    const int tok1 = tok0 + 8;
    const int qv0 = mask[z * NTOK + tok0];
    const int qv1 = mask[z * NTOK + tok1];
    const float inv0 = (qv0 && l0 > 0.f) ? 1.0f / l0 : 0.f;
    const float inv1 = (qv1 && l1 > 0.f) ? 1.0f / l1 : 0.f;

    #pragma unroll
    for (int nt = 0; nt < 8; nt++) {
        int dk = nt * 8 + 2 * tg;
        size_t i0 = ((size_t)(z * NTOK + tok0)) * DMODEL + h * DK + dk;
        size_t i1 = ((size_t)(z * NTOK + tok1)) * DMODEL + h * DK + dk;
        uint32_t hh, ll;
        split2(O[nt][0] * inv0, O[nt][1] * inv0, hh, ll);
        *(uint32_t*)&Ch[i0] = hh; *(uint32_t*)&Cl[i0] = ll;
        split2(O[nt][2] * inv1, O[nt][3] * inv1, hh, ll);
        *(uint32_t*)&Ch[i1] = hh; *(uint32_t*)&Cl[i1] = ll;
    }
}

// ---------------------------------------------------------------------------
// Host entry
// ---------------------------------------------------------------------------
extern "C" void kernel_launch(void* const* d_in, const int* in_sizes, int n_in,
                              void* d_out, int out_size)
{
    const float* x     = (const float*)d_in[0];
    const int*   mask  = (const int*)  d_in[1];
    const float* qproj = (const float*)d_in[2];
    const float* kproj = (const float*)d_in[3];
    const float* vproj = (const float*)d_in[4];
    const float* qbias = (const float*)d_in[5];
    const float* kbias = (const float*)d_in[6];
    const float* vbias = (const float*)d_in[7];
    const float* outw  = (const float*)d_in[8];
    float* out = (float*)d_out;

    __nv_bfloat16 *Xh, *Xl, *BQh, *BQl, *BKh, *BKl, *BVh, *BVl, *Wh, *Wl;
    __nv_bfloat16 *Ch, *Cl, *Qh, *Ql, *Kh, *Kl, *Vth, *Vtl;
    cudaGetSymbolAddress((void**)&Xh,  g_Xh);
    cudaGetSymbolAddress((void**)&Xl,  g_Xl);
    cudaGetSymbolAddress((void**)&BQh, g_BQh);
    cudaGetSymbolAddress((void**)&BQl, g_BQl);
    cudaGetSymbolAddress((void**)&BKh, g_BKh);
    cudaGetSymbolAddress((void**)&BKl, g_BKl);
    cudaGetSymbolAddress((void**)&BVh, g_BVh);
    cudaGetSymbolAddress((void**)&BVl, g_BVl);
    cudaGetSymbolAddress((void**)&Wh,  g_Wh);
    cudaGetSymbolAddress((void**)&Wl,  g_Wl);
    cudaGetSymbolAddress((void**)&Ch,  g_Ch);
    cudaGetSymbolAddress((void**)&Cl,  g_Cl);
    cudaGetSymbolAddress((void**)&Qh,  g_Qh);
    cudaGetSymbolAddress((void**)&Ql,  g_Ql);
    cudaGetSymbolAddress((void**)&Kh,  g_Kh);
    cudaGetSymbolAddress((void**)&Kl,  g_Kl);
    cudaGetSymbolAddress((void**)&Vth, g_Vth);
    cudaGetSymbolAddress((void**)&Vtl, g_Vtl);

    static bool attr_set = false;
    if (!attr_set) {
        cudaFuncSetAttribute(attn_mma,
                             cudaFuncAttributeMaxDynamicSharedMemorySize, 2 * STAGE_B);
        cudaFuncSetAttribute(gemm_bf3_qkv_fused,
                             cudaFuncAttributeMaxDynamicSharedMemorySize, F2_SMEM);
        cudaFuncSetAttribute(gemm_bf3_out,
                             cudaFuncAttributeMaxDynamicSharedMemorySize, 2 * G_STAGE);
        attr_set = true;
    }

    // input splits
    split_any4_kernel<<<1024, 256>>>((const float4*)x, (uint2*)Xh, (uint2*)Xl,
                                     ROWS * DMODEL / 4);
    split_proj3_kernel<<<dim3(DMODEL / 64, HEADS, 3), 256>>>(
        qproj, kproj, vproj, BQh, BQl, BKh, BKl, BVh, BVl);
    split_any4_kernel<<<512, 256>>>((const float4*)outw, (uint2*)Wh, (uint2*)Wl,
                                    DMODEL * DMODEL / 4);

    // fused QKV projection (64-row tiles, 2 CTAs/SM, split epilogues)
    gemm_bf3_qkv_fused<<<dim3(HEADS, ROWS / 64), 256, F2_SMEM>>>(
        Xh, Xl, BQh, BQl, BKh, BKl, BVh, BVl,
        qbias, kbias, vbias, Qh, Ql, Kh, Kl, Vth, Vtl);

    // attention (mma.sync, cp.async pipelined, LDSM frags)
    attn_mma<<<dim3(NTOK / 64, ZH), 128, 2 * STAGE_B>>>(
        Qh, Ql, Kh, Kl, Vth, Vtl, mask, Ch, Cl);

    // output projection
    gemm_bf3_out<<<dim3(DMODEL / 64, ROWS / 128), 256, 2 * G_STAGE>>>(
        Ch, Cl, Wh, Wl, out);
}

// round 17
// speedup vs baseline: 1.1140x; 1.0194x over previous
#include <cuda_runtime.h>
#include <cuda_bf16.h>
#include <cstdint>

// Problem constants
#define ZB     2
#define NTOK   2048
#define DMODEL 1024
#define HEADS  16
#define DK     64
#define ROWS   (ZB * NTOK)          // 4096
#define SCALE  0.125f               // DK^-0.5
#define ZH     (ZB * HEADS)         // 32

// ---------------------------------------------------------------------------
// Device scratch (no runtime allocation allowed)
// ---------------------------------------------------------------------------
__device__ __nv_bfloat16 g_Xh[ROWS * DMODEL];   // x split
__device__ __nv_bfloat16 g_Xl[ROWS * DMODEL];
__device__ __nv_bfloat16 g_BQh[HEADS * DK * DMODEL];  // proj split, [h][n][k]
__device__ __nv_bfloat16 g_BQl[HEADS * DK * DMODEL];
__device__ __nv_bfloat16 g_BKh[HEADS * DK * DMODEL];
__device__ __nv_bfloat16 g_BKl[HEADS * DK * DMODEL];
__device__ __nv_bfloat16 g_BVh[HEADS * DK * DMODEL];
__device__ __nv_bfloat16 g_BVl[HEADS * DK * DMODEL];
__device__ __nv_bfloat16 g_Wh[DMODEL * DMODEL]; // out_w split ([n][k] = native)
__device__ __nv_bfloat16 g_Wl[DMODEL * DMODEL];
__device__ __nv_bfloat16 g_Ch[ROWS * DMODEL];   // ctx split (attention output)
__device__ __nv_bfloat16 g_Cl[ROWS * DMODEL];

// pre-split QKV (written directly by GEMM epilogues)
__device__ __nv_bfloat16 g_Qh[ZH * NTOK * DK];  // [zh][n][dk], SCALE folded
__device__ __nv_bfloat16 g_Ql[ZH * NTOK * DK];
__device__ __nv_bfloat16 g_Kh[ZH * NTOK * DK];  // [zh][key][dk]
__device__ __nv_bfloat16 g_Kl[ZH * NTOK * DK];
__device__ __nv_bfloat16 g_Vth[ZH * DK * NTOK]; // transposed: [zh][dk][key]
__device__ __nv_bfloat16 g_Vtl[ZH * DK * NTOK];

extern __shared__ unsigned char smem_dyn[];

// ---------------------------------------------------------------------------
// helpers
// ---------------------------------------------------------------------------
__device__ __forceinline__ uint32_t packb(__nv_bfloat16 x, __nv_bfloat16 y) {
    return (uint32_t)__bfloat16_as_ushort(x) |
           ((uint32_t)__bfloat16_as_ushort(y) << 16);
}
__device__ __forceinline__ void split1(float x, __nv_bfloat16& h, __nv_bfloat16& l) {
    h = __float2bfloat16(x);
    l = __float2bfloat16(x - __bfloat162float(h));
}
__device__ __forceinline__ void split2(float x, float y, uint32_t& hi, uint32_t& lo) {
    __nv_bfloat16 xh, xl, yh, yl;
    split1(x, xh, xl);
    split1(y, yh, yl);
    hi = packb(xh, yh);
    lo = packb(xl, yl);
}

__device__ __forceinline__ void mma4(float* C, const uint32_t* a,
                                     uint32_t b0, uint32_t b1)
{
    asm volatile(
        "mma.sync.aligned.m16n8k16.row.col.f32.bf16.bf16.f32 "
        "{%0,%1,%2,%3},{%4,%5,%6,%7},{%8,%9},{%0,%1,%2,%3};\n"
        : "+f"(C[0]), "+f"(C[1]), "+f"(C[2]), "+f"(C[3])
        : "r"(a[0]), "r"(a[1]), "r"(a[2]), "r"(a[3]), "r"(b0), "r"(b1));
}

__device__ __forceinline__ void ldsm4(uint32_t* r, uint32_t addr) {
    asm volatile("ldmatrix.sync.aligned.m8n8.x4.shared.b16 {%0,%1,%2,%3}, [%4];"
                 : "=r"(r[0]), "=r"(r[1]), "=r"(r[2]), "=r"(r[3]) : "r"(addr));
}

__device__ __forceinline__ void cp_async16(uint32_t dst, const void* src) {
    asm volatile("cp.async.cg.shared.global [%0], [%1], 16;" :: "r"(dst), "l"(src));
}
__device__ __forceinline__ void cp_async4(uint32_t dst, const void* src) {
    asm volatile("cp.async.ca.shared.global [%0], [%1], 4;" :: "r"(dst), "l"(src));
}
__device__ __forceinline__ void cp_commit() {
    asm volatile("cp.async.commit_group;");
}
template <int N>
__device__ __forceinline__ void cp_wait() {
    asm volatile("cp.async.wait_group %0;" :: "n"(N));
}

// ---------------------------------------------------------------------------
// Vectorized elementwise split: fp32 -> (hi, lo) bf16
// ---------------------------------------------------------------------------
__global__ void split_any4_kernel(const float4* __restrict__ in,
                                  uint2* __restrict__ hi,
                                  uint2* __restrict__ lo, int n4)
{
    for (int i = blockIdx.x * blockDim.x + threadIdx.x; i < n4;
         i += gridDim.x * blockDim.x) {
        float4 v = in[i];
        uint32_t h0, l0, h1, l1;
        split2(v.x, v.y, h0, l0);
        split2(v.z, v.w, h1, l1);
        hi[i] = make_uint2(h0, h1);
        lo[i] = make_uint2(l0, l1);
    }
}

// ---------------------------------------------------------------------------
// Proj split + transpose for Q,K,V in one launch (blockIdx.z selects).
// proj[h][d][n] (fp32) -> B[h][n][d] hi/lo (bf16). grid=(16, HEADS, 3)
// ---------------------------------------------------------------------------
__global__ __launch_bounds__(256) void split_proj3_kernel(
    const float* __restrict__ pq, const float* __restrict__ pk,
    const float* __restrict__ pv,
    __nv_bfloat16* __restrict__ qh, __nv_bfloat16* __restrict__ ql,
    __nv_bfloat16* __restrict__ kh, __nv_bfloat16* __restrict__ kl,
    __nv_bfloat16* __restrict__ vh, __nv_bfloat16* __restrict__ vl)
{
    const int dt = blockIdx.x;
    const int h  = blockIdx.y;
    const int w  = blockIdx.z;
    const float* proj = (w == 0) ? pq : (w == 1) ? pk : pv;
    __nv_bfloat16* Bh = (w == 0) ? qh : (w == 1) ? kh : vh;
    __nv_bfloat16* Bl = (w == 0) ? ql : (w == 1) ? kl : vl;

    const int tid = threadIdx.x;
    __shared__ float tile[64][65];

    const float* src = proj + ((size_t)h * DMODEL + dt * 64) * DK;
    #pragma unroll
    for (int it = 0; it < 4; it++) {
        int i4 = tid + it * 256;
        int r  = i4 >> 4;
        int c4 = (i4 & 15) * 4;
        float4 v = *(const float4*)(src + (size_t)r * DK + c4);
        tile[r][c4 + 0] = v.x; tile[r][c4 + 1] = v.y;
        tile[r][c4 + 2] = v.z; tile[r][c4 + 3] = v.w;
    }
    __syncthreads();
    #pragma unroll
    for (int it = 0; it < 16; it++) {
        int o = tid + it * 256;
        int n = o >> 6;
        int j = o & 63;
        float x = tile[j][n];
        __nv_bfloat16 hh, ll;
        split1(x, hh, ll);
        size_t idx = ((size_t)h * DK + n) * DMODEL + dt * 64 + j;
        Bh[idx] = hh;
        Bl[idx] = ll;
    }
}

// ---------------------------------------------------------------------------
// FUSED QKV bf16x3 MMA GEMM, occupancy-tuned: 64-row x 64-col x 3-output tile.
// 8 warps = 4 row-groups (16 rows) x 2 col-halves (32 cols); A staged once.
// 2-stage cp.async, 40960 B/stage -> 81920 B SMEM -> 2 CTAs/SM.
// grid = (HEADS, ROWS/64)
// ---------------------------------------------------------------------------
#define F2_AH    0
#define F2_AL    5120
#define F2_B     10240      // + w*10240 (hi), +5120 (lo)
#define F2_SZ    40960
#define F2_SMEM  (2 * F2_SZ)   // 81920

__global__ __launch_bounds__(256, 2) void gemm_bf3_qkv_fused(
    const __nv_bfloat16* __restrict__ Xh, const __nv_bfloat16* __restrict__ Xl,
    const __nv_bfloat16* __restrict__ BQh, const __nv_bfloat16* __restrict__ BQl,
    const __nv_bfloat16* __restrict__ BKh, const __nv_bfloat16* __restrict__ BKl,
    const __nv_bfloat16* __restrict__ BVh, const __nv_bfloat16* __restrict__ BVl,
    const float* __restrict__ qbias, const float* __restrict__ kbias,
    const float* __restrict__ vbias,
    __nv_bfloat16* __restrict__ Qh_o, __nv_bfloat16* __restrict__ Ql_o,
    __nv_bfloat16* __restrict__ Kh_o, __nv_bfloat16* __restrict__ Kl_o,
    __nv_bfloat16* __restrict__ Vth_o, __nv_bfloat16* __restrict__ Vtl_o)
{
    const int h  = blockIdx.x;
    const int mb = blockIdx.y;
    const int tid  = threadIdx.x;
    const int warp = tid >> 5;
    const int lane = tid & 31;
    const int warpRow = warp & 3;       // 16-row group
    const int warpCol = warp >> 2;      // 32-col half
    const uint32_t sbase = (uint32_t)__cvta_generic_to_shared(smem_dyn);

    const __nv_bfloat16* Ahb = Xh + (size_t)mb * 64 * DMODEL;
    const __nv_bfloat16* Alb = Xl + (size_t)mb * 64 * DMODEL;
    const __nv_bfloat16* Bh_[3] = { BQh + (size_t)h * DK * DMODEL,
                                    BKh + (size_t)h * DK * DMODEL,
                                    BVh + (size_t)h * DK * DMODEL };
    const __nv_bfloat16* Bl_[3] = { BQl + (size_t)h * DK * DMODEL,
                                    BKl + (size_t)h * DK * DMODEL,
                                    BVl + (size_t)h * DK * DMODEL };

    const int rA = lane & 15, cAo = (lane & 16) >> 1;
    const int rB = (lane & 7) | ((lane & 16) >> 1), cBo = lane & 8;
    const uint32_t offA = (uint32_t)(((warpRow * 16 + rA) * 40 + cAo) * 2);
    const uint32_t offB = (uint32_t)((rB * 40 + cBo) * 2);

    const int cr = tid >> 2;
    const int cs = tid & 3;
    const uint32_t so = (uint32_t)(cr * 80 + cs * 16);

    auto issue = [&](int kcid, int stage) {
        const uint32_t sb = sbase + stage * F2_SZ;
        const size_t go = (size_t)cr * DMODEL + kcid * 32 + cs * 8;
        cp_async16(sb + F2_AH + so, Ahb + go);
        cp_async16(sb + F2_AL + so, Alb + go);
        #pragma unroll
        for (int w = 0; w < 3; w++) {
            const uint32_t bw = sb + F2_B + w * 10240;
            cp_async16(bw + so,        Bh_[w] + go);
            cp_async16(bw + 5120 + so, Bl_[w] + go);
        }
    };

    float O[3][4][4];
    #pragma unroll
    for (int w = 0; w < 3; w++)
        #pragma unroll
        for (int nt = 0; nt < 4; nt++)
            O[w][nt][0] = O[w][nt][1] = O[w][nt][2] = O[w][nt][3] = 0.f;

    issue(0, 0); cp_commit();

    for (int i = 0; i < 32; i++) {
        if (i + 1 < 32) {
            issue(i + 1, (i + 1) & 1);
            cp_commit();
            cp_wait<1>();
        } else {
            cp_wait<0>();
        }
        __syncthreads();

        const uint32_t sb = sbase + (i & 1) * F2_SZ;
        #pragma unroll
        for (int ks = 0; ks < 2; ks++) {
            uint32_t ah[4], al[4];
            ldsm4(ah, sb + F2_AH + offA + ks * 32);
            ldsm4(al, sb + F2_AL + offA + ks * 32);
            #pragma unroll
            for (int w = 0; w < 3; w++) {
                const uint32_t bw = sb + F2_B + w * 10240;
                #pragma unroll
                for (int p = 0; p < 2; p++) {
                    uint32_t bh[4], bl[4];
                    uint32_t kb = bw + offB + (warpCol * 32 + p * 16) * 80 + ks * 32;
                    ldsm4(bh, kb);
                    ldsm4(bl, kb + 5120);
                    mma4(O[w][2 * p],     ah, bh[0], bh[1]);
                    mma4(O[w][2 * p],     ah, bl[0], bl[1]);
                    mma4(O[w][2 * p],     al, bh[0], bh[1]);
                    mma4(O[w][2 * p + 1], ah, bh[2], bh[3]);
                    mma4(O[w][2 * p + 1], ah, bl[2], bl[3]);
                    mma4(O[w][2 * p + 1], al, bh[2], bh[3]);
                }
            }
        }
        __syncthreads();
    }

    // ---- epilogues ----
    const int g = lane >> 2, tg = lane & 3;
    const int row0 = mb * 64 + warpRow * 16 + g, row1 = row0 + 8;
    const int z = row0 >> 11, n0 = row0 & (NTOK - 1), n1 = row1 & (NTOK - 1);
    const int zh = z * HEADS + h;
    const size_t baseT = (size_t)zh * DK * NTOK;

    #pragma unroll
    for (int nt = 0; nt < 4; nt++) {
        int col = warpCol * 32 + nt * 8 + 2 * tg;
        uint32_t hh, ll;

        {
            float b0 = qbias[h * DK + col], b1 = qbias[h * DK + col + 1];
            size_t i0 = ((size_t)zh * NTOK + n0) * DK + col;
            size_t i1 = ((size_t)zh * NTOK + n1) * DK + col;
            split2((O[0][nt][0] + b0) * SCALE, (O[0][nt][1] + b1) * SCALE, hh, ll);
            *(uint32_t*)&Qh_o[i0] = hh; *(uint32_t*)&Ql_o[i0] = ll;
            split2((O[0][nt][2] + b0) * SCALE, (O[0][nt][3] + b1) * SCALE, hh, ll);
            *(uint32_t*)&Qh_o[i1] = hh; *(uint32_t*)&Ql_o[i1] = ll;
        }
        {
            float b0 = kbias[h * DK + col], b1 = kbias[h * DK + col + 1];
            size_t i0 = ((size_t)zh * NTOK + n0) * DK + col;
            size_t i1 = ((size_t)zh * NTOK + n1) * DK + col;
            split2(O[1][nt][0] + b0, O[1][nt][1] + b1, hh, ll);
            *(uint32_t*)&Kh_o[i0] = hh; *(uint32_t*)&Kl_o[i0] = ll;
            split2(O[1][nt][2] + b0, O[1][nt][3] + b1, hh, ll);
            *(uint32_t*)&Kh_o[i1] = hh; *(uint32_t*)&Kl_o[i1] = ll;
        }
        {
            float b0 = vbias[h * DK + col], b1 = vbias[h * DK + col + 1];
            #pragma unroll
            for (int j = 0; j < 2; j++) {
                float v0 = O[2][nt][j]     + (j ? b1 : b0);
                float v1 = O[2][nt][2 + j] + (j ? b1 : b0);
                __nv_bfloat16 bh_, bl_;
                split1(v0, bh_, bl_);
                Vth_o[baseT + (size_t)(col + j) * NTOK + n0] = bh_;
                Vtl_o[baseT + (size_t)(col + j) * NTOK + n0] = bl_;
                split1(v1, bh_, bl_);
                Vth_o[baseT + (size_t)(col + j) * NTOK + n1] = bh_;
                Vtl_o[baseT + (size_t)(col + j) * NTOK + n1] = bl_;
            }
        }
    }
}

// ---------------------------------------------------------------------------
// Out-proj bf16x3 MMA GEMM, occupancy-tuned: 64-row x 64-col tile.
// 8 warps = 4 row-groups x 2 col-halves. 2-stage cp.async, 20480 B/stage ->
// 40960 B SMEM. __launch_bounds__(256, 3) -> 3 CTAs/SM (24 warps).
// grid = (DMODEL/64, ROWS/64)
// ---------------------------------------------------------------------------
#define P_AH     0
#define P_AL     5120
#define P_BH     10240
#define P_BL     15360
#define P_SZ     20480
#define P_SMEM   (2 * P_SZ)    // 40960

__global__ __launch_bounds__(256, 3) void gemm_bf3_out64(
    const __nv_bfloat16* __restrict__ Ah, const __nv_bfloat16* __restrict__ Al,
    const __nv_bfloat16* __restrict__ Bh, const __nv_bfloat16* __restrict__ Bl,
    float* __restrict__ Out)
{
    const int cb = blockIdx.x;
    const int mb = blockIdx.y;
    const int tid  = threadIdx.x;
    const int warp = tid >> 5;
    const int lane = tid & 31;
    const int warpRow = warp & 3;
    const int warpCol = warp >> 2;
    const uint32_t sbase = (uint32_t)__cvta_generic_to_shared(smem_dyn);

    const __nv_bfloat16* Ahb = Ah + (size_t)mb * 64 * DMODEL;
    const __nv_bfloat16* Alb = Al + (size_t)mb * 64 * DMODEL;
    const __nv_bfloat16* Bhb = Bh + (size_t)cb * 64 * DMODEL;
    const __nv_bfloat16* Blb = Bl + (size_t)cb * 64 * DMODEL;

    const int rA = lane & 15, cAo = (lane & 16) >> 1;
    const int rB = (lane & 7) | ((lane & 16) >> 1), cBo = lane & 8;
    const uint32_t offA = (uint32_t)(((warpRow * 16 + rA) * 40 + cAo) * 2);
    const uint32_t offB = (uint32_t)((rB * 40 + cBo) * 2);

    const int cr = tid >> 2;
    const int cs = tid & 3;
    const uint32_t so = (uint32_t)(cr * 80 + cs * 16);

    auto issue = [&](int kcid, int stage) {
        const uint32_t sb = sbase + stage * P_SZ;
        const size_t go = (size_t)cr * DMODEL + kcid * 32 + cs * 8;
        cp_async16(sb + P_AH + so, Ahb + go);
        cp_async16(sb + P_AL + so, Alb + go);
        cp_async16(sb + P_BH + so, Bhb + go);
        cp_async16(sb + P_BL + so, Blb + go);
    };

    float O[4][4];
    #pragma unroll
    for (int nt = 0; nt < 4; nt++)
        O[nt][0] = O[nt][1] = O[nt][2] = O[nt][3] = 0.f;

    issue(0, 0); cp_commit();

    for (int i = 0; i < 32; i++) {
        if (i + 1 < 32) {
            issue(i + 1, (i + 1) & 1);
            cp_commit();
            cp_wait<1>();
        } else {
            cp_wait<0>();
        }
        __syncthreads();

        const uint32_t sb = sbase + (i & 1) * P_SZ;
        #pragma unroll
        for (int ks = 0; ks < 2; ks++) {
            uint32_t ah[4], al[4];
            ldsm4(ah, sb + P_AH + offA + ks * 32);
            ldsm4(al, sb + P_AL + offA + ks * 32);
            #pragma unroll
            for (int p = 0; p < 2; p++) {
                uint32_t bh[4], bl[4];
                uint32_t kb = sb + offB + (warpCol * 32 + p * 16) * 80 + ks * 32;
                ldsm4(bh, kb + P_BH);
                ldsm4(bl, kb + P_BL);
                mma4(O[2 * p],     ah, bh[0], bh[1]);
                mma4(O[2 * p],     ah, bl[0], bl[1]);
                mma4(O[2 * p],     al, bh[0], bh[1]);
                mma4(O[2 * p + 1], ah, bh[2], bh[3]);
                mma4(O[2 * p + 1], ah, bl[2], bl[3]);
                mma4(O[2 * p + 1], al, bh[2], bh[3]);
            }
        }
        __syncthreads();
    }

    const int g = lane >> 2, tg = lane & 3;
    const int row0 = mb * 64 + warpRow * 16 + g, row1 = row0 + 8;

    #pragma unroll
    for (int nt = 0; nt < 4; nt++) {
        int col = cb * 64 + warpCol * 32 + nt * 8 + 2 * tg;
        *(float2*)&Out[(size_t)row0 * DMODEL + col] = make_float2(O[nt][0], O[nt][1]);
        *(float2*)&Out[(size_t)row1 * DMODEL + col] = make_float2(O[nt][2], O[nt][3]);
    }
}

// ---------------------------------------------------------------------------
// Flash attention: bf16x3 MMA + cp.async 2-stage pipeline + ldmatrix frags.
// (round-9 proven version) Block = 128 threads, grid = (NTOK/64, ZH)
// ---------------------------------------------------------------------------
#define TILE_B      9216        // 64 * 72 * 2
#define STAGE_B     37120       // 4*TILE_B + 256
#define OFF_KH      0
#define OFF_KL      (TILE_B)
#define OFF_VH      (2 * TILE_B)
#define OFF_VL      (3 * TILE_B)
#define OFF_MK      (4 * TILE_B)

__global__ __launch_bounds__(128) void attn_mma(
    const __nv_bfloat16* __restrict__ Qh_g, const __nv_bfloat16* __restrict__ Ql_g,
    const __nv_bfloat16* __restrict__ Kh_g, const __nv_bfloat16* __restrict__ Kl_g,
    const __nv_bfloat16* __restrict__ Vth_g, const __nv_bfloat16* __restrict__ Vtl_g,
    const int* __restrict__ mask,
    __nv_bfloat16* __restrict__ Ch, __nv_bfloat16* __restrict__ Cl)
{
    const int qt   = blockIdx.x;
    const int zh   = blockIdx.y;
    const int z    = zh >> 4;
    const int h    = zh & 15;
    const int tid  = threadIdx.x;
    const int warp = tid >> 5;
    const int lane = tid & 31;
    const int g    = lane >> 2;
    const int tg   = lane & 3;

    typedef __nv_bfloat16(*tile_t)[72];
    const size_t base  = (size_t)zh * NTOK * DK;
    const size_t baseT = (size_t)zh * DK * NTOK;
    const uint32_t smem_u32 = (uint32_t)__cvta_generic_to_shared(smem_dyn);

    const int rA = lane & 15, cA = (lane & 16) >> 1;
    const int rB = (lane & 7) | ((lane & 16) >> 1), cB = lane & 8;
    const uint32_t offQ = (uint32_t)(((warp * 16 + rA) * 72 + cA) * 2);
    const uint32_t offF = (uint32_t)((rB * 72 + cB) * 2);

    const int lrow[4] = { tid >> 3, (tid + 128) >> 3, (tid + 256) >> 3, (tid + 384) >> 3 };
    const int lc8 = (tid & 7) * 8;

    {
        tile_t sQh = (tile_t)(smem_dyn + OFF_KH);
        tile_t sQl = (tile_t)(smem_dyn + OFF_KL);
        const __nv_bfloat16* gq_h = Qh_g + base + (size_t)qt * 64 * DK;
        const __nv_bfloat16* gq_l = Ql_g + base + (size_t)qt * 64 * DK;
        #pragma unroll
        for (int it = 0; it < 4; it++) {
            int row = lrow[it];
            *(uint4*)&sQh[row][lc8] = *(const uint4*)(gq_h + (size_t)row * DK + lc8);
            *(uint4*)&sQl[row][lc8] = *(const uint4*)(gq_l + (size_t)row * DK + lc8);
        }
    }
    __syncthreads();

    uint32_t Qh[4][4], Ql[4][4];
    #pragma unroll
    for (int kk = 0; kk < 4; kk++) {
        ldsm4(Qh[kk], smem_u32 + OFF_KH + offQ + kk * 32);
        ldsm4(Ql[kk], smem_u32 + OFF_KL + offQ + kk * 32);
    }
    __syncthreads();

    auto issue_tile = [&](int kt, int stage) {
        const uint32_t sb = smem_u32 + stage * STAGE_B;
        const __nv_bfloat16* gkh = Kh_g + base + (size_t)kt * 64 * DK;
        const __nv_bfloat16* gkl = Kl_g + base + (size_t)kt * 64 * DK;
        const __nv_bfloat16* gvh = Vth_g + baseT + kt * 64;
        const __nv_bfloat16* gvl = Vtl_g + baseT + kt * 64;
        #pragma unroll
        for (int it = 0; it < 4; it++) {
            int row = lrow[it];
            uint32_t rowoff = row * 144 + lc8 * 2;
            cp_async16(sb + OFF_KH + rowoff, gkh + (size_t)row * DK + lc8);
            cp_async16(sb + OFF_KL + rowoff, gkl + (size_t)row * DK + lc8);
            cp_async16(sb + OFF_VH + rowoff, gvh + (size_t)row * NTOK + lc8);
            cp_async16(sb + OFF_VL + rowoff, gvl + (size_t)row * NTOK + lc8);
        }
        if (tid < 64)
            cp_async4(sb + OFF_MK + tid * 4, mask + z * NTOK + kt * 64 + tid);
    };

    float O[8][4];
    #pragma unroll
    for (int nt = 0; nt < 8; nt++)
        O[nt][0] = O[nt][1] = O[nt][2] = O[nt][3] = 0.f;
    float m0 = -1e30f, m1 = -1e30f, l0 = 0.f, l1 = 0.f;

    issue_tile(0, 0);
    cp_commit();

    for (int kt = 0; kt < NTOK / 64; kt++) {
        const int cur = kt & 1;
        if (kt + 1 < NTOK / 64) {
            issue_tile(kt + 1, cur ^ 1);
            cp_commit();
            cp_wait<1>();
        } else {
            cp_wait<0>();
        }
        __syncthreads();

        const uint32_t sb = smem_u32 + cur * STAGE_B;
        int* smk = (int*)(smem_dyn + cur * STAGE_B + OFF_MK);

        float S[8][4];
        #pragma unroll
        for (int p = 0; p < 4; p++) {
            S[2*p][0] = S[2*p][1] = S[2*p][2] = S[2*p][3] = 0.f;
            S[2*p+1][0] = S[2*p+1][1] = S[2*p+1][2] = S[2*p+1][3] = 0.f;
            #pragma unroll
            for (int kk = 0; kk < 4; kk++) {
                uint32_t bh[4], bl[4];
                uint32_t kbb = sb + offF + p * 2304 + kk * 32;
                ldsm4(bh, kbb + OFF_KH);
                ldsm4(bl, kbb + OFF_KL);
                mma4(S[2*p],     Qh[kk], bh[0], bh[1]);
                mma4(S[2*p],     Qh[kk], bl[0], bl[1]);
                mma4(S[2*p],     Ql[kk], bh[0], bh[1]);
                mma4(S[2*p+1],   Qh[kk], bh[2], bh[3]);
                mma4(S[2*p+1],   Qh[kk], bl[2], bl[3]);
                mma4(S[2*p+1],   Ql[kk], bh[2], bh[3]);
            }
        }

        float mx0 = -1e30f, mx1 = -1e30f;
        #pragma unroll
        for (int nt = 0; nt < 8; nt++) {
            #pragma unroll
            for (int j = 0; j < 2; j++) {
                int key = nt * 8 + 2 * tg + j;
                bool ok = smk[key] != 0;
                float v0 = ok ? S[nt][j]     : -1e9f;
                float v1 = ok ? S[nt][2 + j] : -1e9f;
                S[nt][j] = v0; S[nt][2 + j] = v1;
                mx0 = fmaxf(mx0, v0); mx1 = fmaxf(mx1, v1);
            }
        }
        mx0 = fmaxf(mx0, __shfl_xor_sync(0xffffffffu, mx0, 1));
        mx0 = fmaxf(mx0, __shfl_xor_sync(0xffffffffu, mx0, 2));
        mx1 = fmaxf(mx1, __shfl_xor_sync(0xffffffffu, mx1, 1));
        mx1 = fmaxf(mx1, __shfl_xor_sync(0xffffffffu, mx1, 2));

        float mn0 = fmaxf(m0, mx0), mn1 = fmaxf(m1, mx1);
        float corr0 = __expf(m0 - mn0), corr1 = __expf(m1 - mn1);
        m0 = mn0; m1 = mn1;

        float ls0 = 0.f, ls1 = 0.f;
        #pragma unroll
        for (int nt = 0; nt < 8; nt++) {
            S[nt][0] = __expf(S[nt][0] - m0); ls0 += S[nt][0];
            S[nt][1] = __expf(S[nt][1] - m0); ls0 += S[nt][1];
            S[nt][2] = __expf(S[nt][2] - m1); ls1 += S[nt][2];
            S[nt][3] = __expf(S[nt][3] - m1); ls1 += S[nt][3];
        }
        ls0 += __shfl_xor_sync(0xffffffffu, ls0, 1);
        ls0 += __shfl_xor_sync(0xffffffffu, ls0, 2);
        ls1 += __shfl_xor_sync(0xffffffffu, ls1, 1);
        ls1 += __shfl_xor_sync(0xffffffffu, ls1, 2);
        l0 = l0 * corr0 + ls0;
        l1 = l1 * corr1 + ls1;

        #pragma unroll
        for (int nt = 0; nt < 8; nt++) {
            O[nt][0] *= corr0; O[nt][1] *= corr0;
            O[nt][2] *= corr1; O[nt][3] *= corr1;
        }

        #pragma unroll
        for (int kk = 0; kk < 4; kk++) {
            uint32_t ah[4], al[4];
            split2(S[2 * kk][0],     S[2 * kk][1],     ah[0], al[0]);
            split2(S[2 * kk][2],     S[2 * kk][3],     ah[1], al[1]);
            split2(S[2 * kk + 1][0], S[2 * kk + 1][1], ah[2], al[2]);
            split2(S[2 * kk + 1][2], S[2 * kk + 1][3], ah[3], al[3]);
            #pragma unroll
            for (int p = 0; p < 4; p++) {
                uint32_t bh[4], bl[4];
                uint32_t vbb = sb + offF + p * 2304 + kk * 32;
                ldsm4(bh, vbb + OFF_VH);
                ldsm4(bl, vbb + OFF_VL);
                mma4(O[2*p],     ah, bh[0], bh[1]);
                mma4(O[2*p],     ah, bl[0], bl[1]);
                mma4(O[2*p],     al, bh[0], bh[1]);
                mma4(O[2*p+1],   ah, bh[2], bh[3]);
                mma4(O[2*p+1],   ah, bl[2], bl[3]);
                mma4(O[2*p+1],   al, bh[2], bh[3]);
            }
        }
        __syncthreads();
    }

    const int tok0 = qt * 64 + warp * 16 + g;
    const int tok1 = tok0 + 8;
    const int qv0 = mask[z * NTOK + tok0];
    const int qv1 = mask[z * NTOK + tok1];
    const float inv0 = (qv0 && l0 > 0.f) ? 1.0f / l0 : 0.f;
    const float inv1 = (qv1 && l1 > 0.f) ? 1.0f / l1 : 0.f;

    #pragma unroll
    for (int nt = 0; nt < 8; nt++) {
        int dk = nt * 8 + 2 * tg;
        size_t i0 = ((size_t)(z * NTOK + tok0)) * DMODEL + h * DK + dk;
        size_t i1 = ((size_t)(z * NTOK + tok1)) * DMODEL + h * DK + dk;
        uint32_t hh, ll;
        split2(O[nt][0] * inv0, O[nt][1] * inv0, hh, ll);
        *(uint32_t*)&Ch[i0] = hh; *(uint32_t*)&Cl[i0] = ll;
        split2(O[nt][2] * inv1, O[nt][3] * inv1, hh, ll);
        *(uint32_t*)&Ch[i1] = hh; *(uint32_t*)&Cl[i1] = ll;
    }
}

// ---------------------------------------------------------------------------
// Host entry
// ---------------------------------------------------------------------------
extern "C" void kernel_launch(void* const* d_in, const int* in_sizes, int n_in,
                              void* d_out, int out_size)
{
    const float* x     = (const float*)d_in[0];
    const int*   mask  = (const int*)  d_in[1];
    const float* qproj = (const float*)d_in[2];
    const float* kproj = (const float*)d_in[3];
    const float* vproj = (const float*)d_in[4];
    const float* qbias = (const float*)d_in[5];
    const float* kbias = (const float*)d_in[6];
    const float* vbias = (const float*)d_in[7];
    const float* outw  = (const float*)d_in[8];
    float* out = (float*)d_out;

    __nv_bfloat16 *Xh, *Xl, *BQh, *BQl, *BKh, *BKl, *BVh, *BVl, *Wh, *Wl;
    __nv_bfloat16 *Ch, *Cl, *Qh, *Ql, *Kh, *Kl, *Vth, *Vtl;
    cudaGetSymbolAddress((void**)&Xh,  g_Xh);
    cudaGetSymbolAddress((void**)&Xl,  g_Xl);
    cudaGetSymbolAddress((void**)&BQh, g_BQh);
    cudaGetSymbolAddress((void**)&BQl, g_BQl);
    cudaGetSymbolAddress((void**)&BKh, g_BKh);
    cudaGetSymbolAddress((void**)&BKl, g_BKl);
    cudaGetSymbolAddress((void**)&BVh, g_BVh);
    cudaGetSymbolAddress((void**)&BVl, g_BVl);
    cudaGetSymbolAddress((void**)&Wh,  g_Wh);
    cudaGetSymbolAddress((void**)&Wl,  g_Wl);
    cudaGetSymbolAddress((void**)&Ch,  g_Ch);
    cudaGetSymbolAddress((void**)&Cl,  g_Cl);
    cudaGetSymbolAddress((void**)&Qh,  g_Qh);
    cudaGetSymbolAddress((void**)&Ql,  g_Ql);
    cudaGetSymbolAddress((void**)&Kh,  g_Kh);
    cudaGetSymbolAddress((void**)&Kl,  g_Kl);
    cudaGetSymbolAddress((void**)&Vth, g_Vth);
    cudaGetSymbolAddress((void**)&Vtl, g_Vtl);

    static bool attr_set = false;
    if (!attr_set) {
        cudaFuncSetAttribute(attn_mma,
                             cudaFuncAttributeMaxDynamicSharedMemorySize, 2 * STAGE_B);
        cudaFuncSetAttribute(gemm_bf3_qkv_fused,
                             cudaFuncAttributeMaxDynamicSharedMemorySize, F2_SMEM);
        cudaFuncSetAttribute(gemm_bf3_out64,
                             cudaFuncAttributeMaxDynamicSharedMemorySize, P_SMEM);
        attr_set = true;
    }

    // input splits
    split_any4_kernel<<<4096, 256>>>((const float4*)x, (uint2*)Xh, (uint2*)Xl,
                                     ROWS * DMODEL / 4);
    split_proj3_kernel<<<dim3(DMODEL / 64, HEADS, 3), 256>>>(
        qproj, kproj, vproj, BQh, BQl, BKh, BKl, BVh, BVl);
    split_any4_kernel<<<1024, 256>>>((const float4*)outw, (uint2*)Wh, (uint2*)Wl,
                                     DMODEL * DMODEL / 4);

    // fused QKV projection (64-row tiles, 2 CTAs/SM, split epilogues)
    gemm_bf3_qkv_fused<<<dim3(HEADS, ROWS / 64), 256, F2_SMEM>>>(
        Xh, Xl, BQh, BQl, BKh, BKl, BVh, BVl,
        qbias, kbias, vbias, Qh, Ql, Kh, Kl, Vth, Vtl);

    // attention (mma.sync, cp.async pipelined, LDSM frags)
    attn_mma<<<dim3(NTOK / 64, ZH), 128, 2 * STAGE_B>>>(
        Qh, Ql, Kh, Kl, Vth, Vtl, mask, Ch, Cl);

    // output projection (64x64 tiles, 3 CTAs/SM)
    gemm_bf3_out64<<<dim3(DMODEL / 64, ROWS / 64), 256, P_SMEM>>>(
        Ch, Cl, Wh, Wl, out);
}